// round 10
// baseline (speedup 1.0000x reference)
#include <cuda_runtime.h>
#include <cuda_fp16.h>
#include <math.h>
#include <stdint.h>

#define S_IMG 16384
#define N_TXT 4096
#define DIM   512

// d_out layout (floats): [loss(1) | sel(4096) | zimg | ztxt | all_pairs | final_logits]
static const size_t OFF_SEL  = 1;
static const size_t OFF_ZIMG = 4097;
static const size_t OFF_ZTXT = 8392705;
static const size_t OFF_AP   = 10489857;   // ODD -> d_out+OFF_AP only 4B-aligned!
static const size_t OFF_FL   = 77598721;   // ODD as well

// ---------------- device scratch (aligned for vector/cp.async access) -------
__device__ __align__(256) float   g_zimg[(size_t)S_IMG * DIM];
__device__ __align__(256) float   g_ztxt[(size_t)N_TXT * DIM];
__device__ __align__(256) __half  g_zimg_h[(size_t)S_IMG * DIM];
__device__ __align__(256) __half  g_ztxt_h[(size_t)N_TXT * DIM];
__device__ float          g_pploss[S_IMG];
__device__ unsigned       g_segmin[N_TXT];
__device__ int            g_sel[N_TXT];
__device__ float          g_rowsum[N_TXT];
__device__ int            g_key_is64;

__device__ __forceinline__ float softplus_f(float z) {
    return fmaxf(z, 0.0f) + log1pf(expf(-fabsf(z)));
}
__device__ __forceinline__ int load_key(const int* __restrict__ key, int i) {
    return g_key_is64 ? key[2 * i] : key[i];
}

// ---------------- portable PTX helpers (compute_103-safe) ----------------
__device__ __forceinline__ uint32_t smem_u32(const void* p) {
    uint32_t a;
    asm("{ .reg .u64 t; cvta.to.shared.u64 t, %1; cvt.u32.u64 %0, t; }" : "=r"(a) : "l"(p));
    return a;
}
__device__ __forceinline__ void cp_async16(uint32_t dst, const void* src) {
    asm volatile("cp.async.cg.shared.global [%0], [%1], 16;" :: "r"(dst), "l"(src));
}
#define CP_COMMIT() asm volatile("cp.async.commit_group;" ::: "memory")
#define CP_WAIT0()  asm volatile("cp.async.wait_group 0;" ::: "memory")
#define CP_WAIT1()  asm volatile("cp.async.wait_group 1;" ::: "memory")

__device__ __forceinline__ void ldmat_x4(uint32_t addr, uint32_t* r) {
    asm volatile("ldmatrix.sync.aligned.m8n8.x4.shared.b16 {%0,%1,%2,%3}, [%4];"
                 : "=r"(r[0]), "=r"(r[1]), "=r"(r[2]), "=r"(r[3]) : "r"(addr));
}
__device__ __forceinline__ void mma16816(float* c, const uint32_t* a, const uint32_t* b) {
    asm volatile(
        "mma.sync.aligned.m16n8k16.row.col.f32.f16.f16.f32 "
        "{%0,%1,%2,%3}, {%4,%5,%6,%7}, {%8,%9}, {%0,%1,%2,%3};"
        : "+f"(c[0]), "+f"(c[1]), "+f"(c[2]), "+f"(c[3])
        : "r"(a[0]), "r"(a[1]), "r"(a[2]), "r"(a[3]), "r"(b[0]), "r"(b[1]));
}

// ---------------------------------------------------------------------------
// K0: init + key dtype probe
// ---------------------------------------------------------------------------
__global__ void init_kernel() {
    int i = blockIdx.x * blockDim.x + threadIdx.x;
    if (i == 0) g_key_is64 = 1;
    if (i < N_TXT) {
        g_segmin[i] = 0x7F800000u;
        g_sel[i]    = S_IMG;
    }
}
__global__ void detect_key_kernel(const int* __restrict__ key32) {
    int i = blockIdx.x * blockDim.x + threadIdx.x;
    if (i < S_IMG / 2 && key32[2 * i + 1] != 0)
        atomicExch(&g_key_is64, 0);
}

// ---------------------------------------------------------------------------
// K1/K2: normalize -> fp32 scratch + fp16 + d_out copy
// ---------------------------------------------------------------------------
__global__ void norm_img_kernel(const float* __restrict__ in, float* __restrict__ out_region) {
    const int row = blockIdx.x, t = threadIdx.x;
    float4 x = ((const float4*)(in + (size_t)row * DIM))[t];
    float ss = x.x * x.x + x.y * x.y + x.z * x.z + x.w * x.w;
    #pragma unroll
    for (int o = 16; o > 0; o >>= 1) ss += __shfl_xor_sync(0xFFFFFFFFu, ss, o);
    __shared__ float w[4];
    if ((t & 31) == 0) w[t >> 5] = ss;
    __syncthreads();
    float sc = 1.0f / (sqrtf(w[0] + w[1] + w[2] + w[3]) + 1e-12f);
    float y[4] = {x.x * sc, x.y * sc, x.z * sc, x.w * sc};
    ((float4*)(g_zimg + (size_t)row * DIM))[t] = make_float4(y[0], y[1], y[2], y[3]);
    size_t base = (size_t)row * DIM + (size_t)t * 4;
    #pragma unroll
    for (int e = 0; e < 4; e++) {
        g_zimg_h[base + e] = __float2half_rn(y[e]);
        out_region[base + e] = y[e];   // scalar: region only 4B-aligned
    }
}
__global__ void norm_txt_kernel(const float* __restrict__ in, float* __restrict__ out_region) {
    const int row = blockIdx.x, t = threadIdx.x;
    float4 x = ((const float4*)(in + (size_t)row * DIM))[t];
    float ss = x.x * x.x + x.y * x.y + x.z * x.z + x.w * x.w;
    #pragma unroll
    for (int o = 16; o > 0; o >>= 1) ss += __shfl_xor_sync(0xFFFFFFFFu, ss, o);
    __shared__ float w[4];
    if ((t & 31) == 0) w[t >> 5] = ss;
    __syncthreads();
    float sc = 1.0f / (sqrtf(w[0] + w[1] + w[2] + w[3]) + 1e-12f);
    float y[4] = {x.x * sc, x.y * sc, x.z * sc, x.w * sc};
    ((float4*)(g_ztxt + (size_t)row * DIM))[t] = make_float4(y[0], y[1], y[2], y[3]);
    size_t base = (size_t)row * DIM + (size_t)t * 4;
    #pragma unroll
    for (int e = 0; e < 4; e++) {
        g_ztxt_h[base + e] = __float2half_rn(y[e]);
        out_region[base + e] = y[e];
    }
}

// ---------------------------------------------------------------------------
// K3: HMMA GEMM  C[m,n] = (ah.bh) * t + bias
// 256x128 CTA tile, 256 threads = 8 warps (4x2), warp tile 64x64, BK=16,
// 3-stage cp.async. smem/stage: (256+128) rows x 48B = 18432 B
// ---------------------------------------------------------------------------
#define BK        16
#define ROW_B     48
#define A_ROWS    256
#define B_ROWS    128
#define A_SB      (A_ROWS * ROW_B)            // 12288
#define STAGE_SB  ((A_ROWS + B_ROWS) * ROW_B) // 18432
#define NSTAGE    3
#define KSTEPS    (DIM / BK)                  // 32

__device__ __forceinline__ void load_stage(uint32_t smBase, int stage,
                                           const __half* Ah, const __half* Bh,
                                           int k0, int tid) {
    const uint32_t base = smBase + stage * STAGE_SB;
    // 384 rows x 2 halves = 768 cp.async ops; 256 threads x 3
    #pragma unroll
    for (int j = 0; j < 3; j++) {
        int idx = j * 256 + tid;          // 0..767
        int row = idx >> 1;
        int half = idx & 1;
        uint32_t soff = (uint32_t)row * ROW_B + half * 16;
        if (row < A_ROWS) {
            cp_async16(base + soff, Ah + (size_t)row * DIM + k0 + half * 8);
        } else {
            int brow = row - A_ROWS;
            cp_async16(base + soff, Bh + (size_t)brow * DIM + k0 + half * 8);
        }
    }
}

__global__ void __launch_bounds__(256, 1)
gemm_hmma_kernel(float* __restrict__ C,
                 const float* __restrict__ log_t_p,
                 const float* __restrict__ bias_p) {
    extern __shared__ char smem[];
    const uint32_t smBase = smem_u32(smem);
    const int tid  = threadIdx.x;
    const int wid  = tid >> 5;
    const int lane = tid & 31;
    const int warp_m = wid & 3;        // 0..3 -> 64-row slab
    const int warp_n = wid >> 2;       // 0..1 -> 64-col slab
    const int rowBase = blockIdx.y * 256;
    const int colBase = blockIdx.x * 128;

    const __half* Ah = g_zimg_h + (size_t)rowBase * DIM;
    const __half* Bh = g_ztxt_h + (size_t)colBase * DIM;

    float acc[4][8][4];   // [m16][n8][frag]
    #pragma unroll
    for (int i = 0; i < 4; i++)
        #pragma unroll
        for (int j = 0; j < 8; j++)
            #pragma unroll
            for (int f = 0; f < 4; f++) acc[i][j][f] = 0.0f;

    const uint32_t aoff = (uint32_t)((warp_m * 64 + (lane & 15)) * ROW_B + (lane >> 4) * 16);
    const uint32_t boff = (uint32_t)(A_SB +
                                     (warp_n * 64 + (lane & 7) + ((lane >> 4) << 3)) * ROW_B +
                                     ((lane >> 3) & 1) * 16);

    load_stage(smBase, 0, Ah, Bh, 0, tid);  CP_COMMIT();
    load_stage(smBase, 1, Ah, Bh, BK, tid); CP_COMMIT();

    #pragma unroll 1
    for (int ks = 0; ks < KSTEPS; ks++) {
        if (ks == KSTEPS - 1) { CP_WAIT0(); } else { CP_WAIT1(); }
        __syncthreads();
        if (ks + 2 < KSTEPS) {
            load_stage(smBase, (ks + 2) % NSTAGE, Ah, Bh, (ks + 2) * BK, tid);
            CP_COMMIT();
        }

        const uint32_t st = smBase + (ks % NSTAGE) * STAGE_SB;
        uint32_t af[4][4], bfr[4][4];

        #pragma unroll
        for (int i = 0; i < 4; i++)
            ldmat_x4(st + aoff + i * 16 * ROW_B, af[i]);
        #pragma unroll
        for (int j = 0; j < 4; j++)
            ldmat_x4(st + boff + j * 16 * ROW_B, bfr[j]);

        #pragma unroll
        for (int i = 0; i < 4; i++)
            #pragma unroll
            for (int j = 0; j < 8; j++)
                mma16816(acc[i][j], af[i], &bfr[j >> 1][(j & 1) * 2]);
    }

    // Epilogue: SCALAR stores only — C is 4B-aligned (OFF_AP is odd).
    const float t = expf(log_t_p[0]);
    const float b = bias_p[0];
    const int mrow0 = rowBase + warp_m * 64 + (lane >> 2);
    const int ncol0 = colBase + warp_n * 64 + 2 * (lane & 3);
    #pragma unroll
    for (int i = 0; i < 4; i++) {
        #pragma unroll
        for (int j = 0; j < 8; j++) {
            size_t r0 = (size_t)(mrow0 + i * 16) * N_TXT + ncol0 + j * 8;
            size_t r1 = r0 + (size_t)8 * N_TXT;
            C[r0 + 0] = acc[i][j][0] * t + b;
            C[r0 + 1] = acc[i][j][1] * t + b;
            C[r1 + 0] = acc[i][j][2] * t + b;
            C[r1 + 1] = acc[i][j][3] * t + b;
        }
    }
}

// ---------------------------------------------------------------------------
// K4: exact fp32 true-positive logits (warp per image) + segment min
// ---------------------------------------------------------------------------
__global__ void tp_kernel(const int* __restrict__ key,
                          const float* __restrict__ log_t_p,
                          const float* __restrict__ bias_p) {
    const int gw = (blockIdx.x * blockDim.x + threadIdx.x) >> 5;
    if (gw >= S_IMG) return;
    const int lane = threadIdx.x & 31;
    const int k = load_key(key, gw);
    const float4* a = (const float4*)(g_zimg + (size_t)gw * DIM);
    const float4* v = (const float4*)(g_ztxt + (size_t)k * DIM);
    float s = 0.0f;
    #pragma unroll
    for (int j = 0; j < 4; j++) {
        float4 x = a[lane + 32 * j], y = v[lane + 32 * j];
        s += x.x * y.x + x.y * y.y + x.z * y.z + x.w * y.w;
    }
    #pragma unroll
    for (int o = 16; o > 0; o >>= 1) s += __shfl_xor_sync(0xFFFFFFFFu, s, o);
    if (lane == 0) {
        float lp = s * expf(log_t_p[0]) + bias_p[0];
        float p = softplus_f(-lp);
        g_pploss[gw] = p;
        atomicMin(&g_segmin[k], __float_as_uint(p));
    }
}

// K5: first-index argmin among exact-min matches
__global__ void argmin_kernel(const int* __restrict__ key) {
    int i = blockIdx.x * blockDim.x + threadIdx.x;
    if (i >= S_IMG) return;
    int k = load_key(key, i);
    if (__float_as_uint(g_pploss[i]) == g_segmin[k])
        atomicMin(&g_sel[k], i);
}

// K6: selected indices (as float) to d_out
__global__ void sel_kernel(float* __restrict__ out_sel) {
    int n = blockIdx.x * blockDim.x + threadIdx.x;
    if (n >= N_TXT) return;
    int sv = g_sel[n];
    out_sel[n] = (float)(sv < S_IMG ? sv : -1);
}

// ---------------------------------------------------------------------------
// K7: final_logits = row gather of all_pairs (bias if invalid) + row loss sums
// ---------------------------------------------------------------------------
__global__ void __launch_bounds__(256)
final_kernel(const float* __restrict__ AP, float* __restrict__ FL,
             const float* __restrict__ bias_p) {
    const int n = blockIdx.x;
    const int sv = g_sel[n];
    const bool valid = sv < S_IMG;
    const float b = bias_p[0];
    const float* src = AP + (size_t)(valid ? sv : 0) * N_TXT;

    float sum = 0.0f;
    for (int j = threadIdx.x; j < N_TXT; j += 256) {
        float v = valid ? src[j] : b;
        FL[(size_t)n * N_TXT + j] = v;
        float lbl = (j == n) ? 1.0f : -1.0f;
        sum += softplus_f(-(lbl * v));
    }
    __shared__ float sm[256];
    sm[threadIdx.x] = sum;
    __syncthreads();
    #pragma unroll
    for (int o = 128; o > 0; o >>= 1) {
        if (threadIdx.x < o) sm[threadIdx.x] += sm[threadIdx.x + o];
        __syncthreads();
    }
    if (threadIdx.x == 0) g_rowsum[n] = sm[0];
}

// K8: final loss reduction (double)
__global__ void loss_kernel(float* __restrict__ out_loss) {
    __shared__ double sd[256];
    double s = 0.0;
    for (int n = threadIdx.x; n < N_TXT; n += 256) s += (double)g_rowsum[n];
    sd[threadIdx.x] = s;
    __syncthreads();
    #pragma unroll
    for (int o = 128; o > 0; o >>= 1) {
        if (threadIdx.x < o) sd[threadIdx.x] += sd[threadIdx.x + o];
        __syncthreads();
    }
    if (threadIdx.x == 0) out_loss[0] = (float)(sd[0] / (double)N_TXT);
}

// ---------------------------------------------------------------------------
extern "C" void kernel_launch(void* const* d_in, const int* in_sizes, int n_in,
                              void* d_out, int out_size) {
    const float* img   = (const float*)d_in[0];
    const float* txt   = (const float*)d_in[1];
    const int*   key   = (const int*)d_in[2];
    const float* log_t = (const float*)d_in[3];
    const float* bias  = (const float*)d_in[4];
    float* out = (float*)d_out;
    (void)in_sizes; (void)n_in; (void)out_size;

    float* out_sel  = out + OFF_SEL;
    float* out_zimg = out + OFF_ZIMG;
    float* out_ztxt = out + OFF_ZTXT;
    float* out_ap   = out + OFF_AP;
    float* out_fl   = out + OFF_FL;

    static int smem_cfg = 0;
    const int smem_bytes = NSTAGE * STAGE_SB;   // 55296
    if (!smem_cfg) {
        cudaFuncSetAttribute(gemm_hmma_kernel,
                             cudaFuncAttributeMaxDynamicSharedMemorySize, smem_bytes);
        smem_cfg = 1;
    }

    init_kernel<<<(N_TXT + 255) / 256, 256>>>();
    detect_key_kernel<<<(S_IMG / 2 + 255) / 256, 256>>>(key);
    norm_img_kernel<<<S_IMG, 128>>>(img, out_zimg);
    norm_txt_kernel<<<N_TXT, 128>>>(txt, out_ztxt);

    dim3 grid(N_TXT / 128, S_IMG / 256);
    gemm_hmma_kernel<<<grid, 256, smem_bytes>>>(out_ap, log_t, bias);

    tp_kernel<<<(S_IMG * 32 + 255) / 256, 256>>>(key, log_t, bias);
    argmin_kernel<<<(S_IMG + 255) / 256, 256>>>(key);
    sel_kernel<<<(N_TXT + 255) / 256, 256>>>(out_sel);

    final_kernel<<<N_TXT, 256>>>(out_ap, out_fl, bias);
    loss_kernel<<<1, 256>>>(out);
}

// round 11
// speedup vs baseline: 1.2521x; 1.2521x over previous
#include <cuda_runtime.h>
#include <cuda_fp16.h>
#include <math.h>
#include <stdint.h>

#define S_IMG 16384
#define N_TXT 4096
#define DIM   512

// d_out layout (floats): [loss(1) | sel(4096) | zimg | ztxt | all_pairs | final_logits]
static const size_t OFF_SEL  = 1;
static const size_t OFF_ZIMG = 4097;
static const size_t OFF_ZTXT = 8392705;
static const size_t OFF_AP   = 10489857;   // ODD -> d_out+OFF_AP only 4B-aligned!
static const size_t OFF_FL   = 77598721;   // ODD as well

// ---------------- device scratch (aligned for vector/cp.async access) -------
__device__ __align__(256) float   g_zimg[(size_t)S_IMG * DIM];
__device__ __align__(256) float   g_ztxt[(size_t)N_TXT * DIM];
__device__ __align__(256) __half  g_zimg_h[(size_t)S_IMG * DIM];
__device__ __align__(256) __half  g_ztxt_h[(size_t)N_TXT * DIM];
__device__ float          g_pploss[S_IMG];
__device__ unsigned       g_segmin[N_TXT];
__device__ int            g_sel[N_TXT];
__device__ float          g_rowsum[N_TXT];
__device__ int            g_key_is64;

__device__ __forceinline__ float softplus_f(float z) {
    return fmaxf(z, 0.0f) + log1pf(expf(-fabsf(z)));
}
__device__ __forceinline__ int load_key(const int* __restrict__ key, int i) {
    return g_key_is64 ? key[2 * i] : key[i];
}

// ---------------- portable PTX helpers (compute_103-safe) ----------------
__device__ __forceinline__ uint32_t smem_u32(const void* p) {
    uint32_t a;
    asm("{ .reg .u64 t; cvta.to.shared.u64 t, %1; cvt.u32.u64 %0, t; }" : "=r"(a) : "l"(p));
    return a;
}
__device__ __forceinline__ void cp_async16(uint32_t dst, const void* src) {
    asm volatile("cp.async.cg.shared.global [%0], [%1], 16;" :: "r"(dst), "l"(src));
}
#define CP_COMMIT() asm volatile("cp.async.commit_group;" ::: "memory")
#define CP_WAIT0()  asm volatile("cp.async.wait_group 0;" ::: "memory")
#define CP_WAIT1()  asm volatile("cp.async.wait_group 1;" ::: "memory")
#define CP_WAIT2()  asm volatile("cp.async.wait_group 2;" ::: "memory")

__device__ __forceinline__ void ldmat_x4(uint32_t addr, uint32_t* r) {
    asm volatile("ldmatrix.sync.aligned.m8n8.x4.shared.b16 {%0,%1,%2,%3}, [%4];"
                 : "=r"(r[0]), "=r"(r[1]), "=r"(r[2]), "=r"(r[3]) : "r"(addr));
}
__device__ __forceinline__ void mma16816(float* c, const uint32_t* a, const uint32_t* b) {
    asm volatile(
        "mma.sync.aligned.m16n8k16.row.col.f32.f16.f16.f32 "
        "{%0,%1,%2,%3}, {%4,%5,%6,%7}, {%8,%9}, {%0,%1,%2,%3};"
        : "+f"(c[0]), "+f"(c[1]), "+f"(c[2]), "+f"(c[3])
        : "r"(a[0]), "r"(a[1]), "r"(a[2]), "r"(a[3]), "r"(b[0]), "r"(b[1]));
}

// ---------------------------------------------------------------------------
// K0: init + key dtype probe
// ---------------------------------------------------------------------------
__global__ void init_kernel() {
    int i = blockIdx.x * blockDim.x + threadIdx.x;
    if (i == 0) g_key_is64 = 1;
    if (i < N_TXT) {
        g_segmin[i] = 0x7F800000u;
        g_sel[i]    = S_IMG;
    }
}
__global__ void detect_key_kernel(const int* __restrict__ key32) {
    int i = blockIdx.x * blockDim.x + threadIdx.x;
    if (i < S_IMG / 2 && key32[2 * i + 1] != 0)
        atomicExch(&g_key_is64, 0);
}

// ---------------------------------------------------------------------------
// K1/K2: normalize -> fp32 scratch + fp16 + d_out copy
// ---------------------------------------------------------------------------
__global__ void norm_img_kernel(const float* __restrict__ in, float* __restrict__ out_region) {
    const int row = blockIdx.x, t = threadIdx.x;
    float4 x = ((const float4*)(in + (size_t)row * DIM))[t];
    float ss = x.x * x.x + x.y * x.y + x.z * x.z + x.w * x.w;
    #pragma unroll
    for (int o = 16; o > 0; o >>= 1) ss += __shfl_xor_sync(0xFFFFFFFFu, ss, o);
    __shared__ float w[4];
    if ((t & 31) == 0) w[t >> 5] = ss;
    __syncthreads();
    float sc = 1.0f / (sqrtf(w[0] + w[1] + w[2] + w[3]) + 1e-12f);
    float y[4] = {x.x * sc, x.y * sc, x.z * sc, x.w * sc};
    ((float4*)(g_zimg + (size_t)row * DIM))[t] = make_float4(y[0], y[1], y[2], y[3]);
    size_t base = (size_t)row * DIM + (size_t)t * 4;
    #pragma unroll
    for (int e = 0; e < 4; e++) {
        g_zimg_h[base + e] = __float2half_rn(y[e]);
        out_region[base + e] = y[e];   // scalar: region only 4B-aligned
    }
}
__global__ void norm_txt_kernel(const float* __restrict__ in, float* __restrict__ out_region) {
    const int row = blockIdx.x, t = threadIdx.x;
    float4 x = ((const float4*)(in + (size_t)row * DIM))[t];
    float ss = x.x * x.x + x.y * x.y + x.z * x.z + x.w * x.w;
    #pragma unroll
    for (int o = 16; o > 0; o >>= 1) ss += __shfl_xor_sync(0xFFFFFFFFu, ss, o);
    __shared__ float w[4];
    if ((t & 31) == 0) w[t >> 5] = ss;
    __syncthreads();
    float sc = 1.0f / (sqrtf(w[0] + w[1] + w[2] + w[3]) + 1e-12f);
    float y[4] = {x.x * sc, x.y * sc, x.z * sc, x.w * sc};
    ((float4*)(g_ztxt + (size_t)row * DIM))[t] = make_float4(y[0], y[1], y[2], y[3]);
    size_t base = (size_t)row * DIM + (size_t)t * 4;
    #pragma unroll
    for (int e = 0; e < 4; e++) {
        g_ztxt_h[base + e] = __float2half_rn(y[e]);
        out_region[base + e] = y[e];
    }
}

// ---------------------------------------------------------------------------
// K3: HMMA GEMM  C[m,n] = (ah.bh) * t + bias   (single fp16 pass)
// 128x128 CTA tile, 256 threads (2x4 warps, 64x32 per warp), BK=32, 4 stages
// Row = 64B data + 16B pad = 80B. smem/stage: 2 tiles x 128 x 80 = 20480 B
// ---------------------------------------------------------------------------
#define BK        32
#define ROW_B     80
#define TILE_SB   (128 * ROW_B)   // 10240
#define STAGE_SB  (2 * TILE_SB)   // 20480
#define NSTAGE    4
#define KSTEPS    (DIM / BK)      // 16

__device__ __forceinline__ void load_stage(uint32_t smBase, int stage,
                                           const __half* Ah, const __half* Bh,
                                           int k0, int tid) {
    const uint32_t base = smBase + stage * STAGE_SB;
    // 2 tiles x 128 rows x 4 chunks(16B) = 1024 ops; 256 threads x 4
    #pragma unroll
    for (int j = 0; j < 4; j++) {
        int idx = j * 256 + tid;         // 0..1023
        int row = idx >> 2;              // 0..255
        int chunk = idx & 3;             // 0..3 (16B each)
        uint32_t soff = (uint32_t)(row & 127) * ROW_B + chunk * 16;
        if (row < 128)
            cp_async16(base + soff, Ah + (size_t)row * DIM + k0 + chunk * 8);
        else
            cp_async16(base + TILE_SB + soff, Bh + (size_t)(row - 128) * DIM + k0 + chunk * 8);
    }
}

__global__ void __launch_bounds__(256, 2)
gemm_hmma_kernel(float* __restrict__ C,
                 const float* __restrict__ log_t_p,
                 const float* __restrict__ bias_p) {
    extern __shared__ char smem[];
    const uint32_t smBase = smem_u32(smem);
    const int tid  = threadIdx.x;
    const int wid  = tid >> 5;
    const int lane = tid & 31;
    const int warp_m = wid & 1;        // 0..1 -> 64-row slab
    const int warp_n = wid >> 1;       // 0..3 -> 32-col slab
    const int rowBase = blockIdx.y * 128;
    const int colBase = blockIdx.x * 128;

    const __half* Ah = g_zimg_h + (size_t)rowBase * DIM;
    const __half* Bh = g_ztxt_h + (size_t)colBase * DIM;

    float acc[4][4][4];
    #pragma unroll
    for (int i = 0; i < 4; i++)
        #pragma unroll
        for (int j = 0; j < 4; j++)
            #pragma unroll
            for (int f = 0; f < 4; f++) acc[i][j][f] = 0.0f;

    const uint32_t aoff = (uint32_t)((warp_m * 64 + (lane & 15)) * ROW_B + (lane >> 4) * 16);
    const uint32_t boff = (uint32_t)(TILE_SB +
                                     (warp_n * 32 + (lane & 7) + ((lane >> 4) << 3)) * ROW_B +
                                     ((lane >> 3) & 1) * 16);

    load_stage(smBase, 0, Ah, Bh, 0 * BK, tid); CP_COMMIT();
    load_stage(smBase, 1, Ah, Bh, 1 * BK, tid); CP_COMMIT();
    load_stage(smBase, 2, Ah, Bh, 2 * BK, tid); CP_COMMIT();

    #pragma unroll 1
    for (int ks = 0; ks < KSTEPS; ks++) {
        // retire the group that filled stage ks%NSTAGE
        if (ks < KSTEPS - 2)       { CP_WAIT2(); }
        else if (ks == KSTEPS - 2) { CP_WAIT1(); }
        else                       { CP_WAIT0(); }
        __syncthreads();
        if (ks + 3 < KSTEPS) {
            load_stage(smBase, (ks + 3) % NSTAGE, Ah, Bh, (ks + 3) * BK, tid);
            CP_COMMIT();
        }

        const uint32_t st = smBase + (ks % NSTAGE) * STAGE_SB;

        #pragma unroll
        for (int kk = 0; kk < 2; kk++) {   // two k16 halves within BK=32
            uint32_t af[4][4], bfr[2][4];
            #pragma unroll
            for (int i = 0; i < 4; i++)
                ldmat_x4(st + aoff + kk * 32 + i * 16 * ROW_B, af[i]);
            #pragma unroll
            for (int j = 0; j < 2; j++)
                ldmat_x4(st + boff + kk * 32 + j * 16 * ROW_B, bfr[j]);
            #pragma unroll
            for (int i = 0; i < 4; i++)
                #pragma unroll
                for (int j = 0; j < 4; j++)
                    mma16816(acc[i][j], af[i], &bfr[j >> 1][(j & 1) * 2]);
        }
    }

    // Epilogue: SCALAR stores only — C is 4B-aligned (OFF_AP is odd).
    const float t = expf(log_t_p[0]);
    const float b = bias_p[0];
    const int mrow0 = rowBase + warp_m * 64 + (lane >> 2);
    const int ncol0 = colBase + warp_n * 32 + 2 * (lane & 3);
    #pragma unroll
    for (int i = 0; i < 4; i++) {
        #pragma unroll
        for (int j = 0; j < 4; j++) {
            size_t r0 = (size_t)(mrow0 + i * 16) * N_TXT + ncol0 + j * 8;
            size_t r1 = r0 + (size_t)8 * N_TXT;
            C[r0 + 0] = acc[i][j][0] * t + b;
            C[r0 + 1] = acc[i][j][1] * t + b;
            C[r1 + 0] = acc[i][j][2] * t + b;
            C[r1 + 1] = acc[i][j][3] * t + b;
        }
    }
}

// ---------------------------------------------------------------------------
// K4: exact fp32 true-positive logits (warp per image) + segment min
// ---------------------------------------------------------------------------
__global__ void tp_kernel(const int* __restrict__ key,
                          const float* __restrict__ log_t_p,
                          const float* __restrict__ bias_p) {
    const int gw = (blockIdx.x * blockDim.x + threadIdx.x) >> 5;
    if (gw >= S_IMG) return;
    const int lane = threadIdx.x & 31;
    const int k = load_key(key, gw);
    const float4* a = (const float4*)(g_zimg + (size_t)gw * DIM);
    const float4* v = (const float4*)(g_ztxt + (size_t)k * DIM);
    float s = 0.0f;
    #pragma unroll
    for (int j = 0; j < 4; j++) {
        float4 x = a[lane + 32 * j], y = v[lane + 32 * j];
        s += x.x * y.x + x.y * y.y + x.z * y.z + x.w * y.w;
    }
    #pragma unroll
    for (int o = 16; o > 0; o >>= 1) s += __shfl_xor_sync(0xFFFFFFFFu, s, o);
    if (lane == 0) {
        float lp = s * expf(log_t_p[0]) + bias_p[0];
        float p = softplus_f(-lp);
        g_pploss[gw] = p;
        atomicMin(&g_segmin[k], __float_as_uint(p));
    }
}

// K5: first-index argmin among exact-min matches
__global__ void argmin_kernel(const int* __restrict__ key) {
    int i = blockIdx.x * blockDim.x + threadIdx.x;
    if (i >= S_IMG) return;
    int k = load_key(key, i);
    if (__float_as_uint(g_pploss[i]) == g_segmin[k])
        atomicMin(&g_sel[k], i);
}

// K6: selected indices (as float) to d_out
__global__ void sel_kernel(float* __restrict__ out_sel) {
    int n = blockIdx.x * blockDim.x + threadIdx.x;
    if (n >= N_TXT) return;
    int sv = g_sel[n];
    out_sel[n] = (float)(sv < S_IMG ? sv : -1);
}

// ---------------------------------------------------------------------------
// K7: final_logits = row gather of all_pairs (bias if invalid) + row loss sums
// ---------------------------------------------------------------------------
__global__ void __launch_bounds__(256)
final_kernel(const float* __restrict__ AP, float* __restrict__ FL,
             const float* __restrict__ bias_p) {
    const int n = blockIdx.x;
    const int sv = g_sel[n];
    const bool valid = sv < S_IMG;
    const float b = bias_p[0];
    const float* src = AP + (size_t)(valid ? sv : 0) * N_TXT;

    float sum = 0.0f;
    for (int j = threadIdx.x; j < N_TXT; j += 256) {
        float v = valid ? src[j] : b;
        FL[(size_t)n * N_TXT + j] = v;
        float lbl = (j == n) ? 1.0f : -1.0f;
        sum += softplus_f(-(lbl * v));
    }
    __shared__ float sm[256];
    sm[threadIdx.x] = sum;
    __syncthreads();
    #pragma unroll
    for (int o = 128; o > 0; o >>= 1) {
        if (threadIdx.x < o) sm[threadIdx.x] += sm[threadIdx.x + o];
        __syncthreads();
    }
    if (threadIdx.x == 0) g_rowsum[n] = sm[0];
}

// K8: final loss reduction (double)
__global__ void loss_kernel(float* __restrict__ out_loss) {
    __shared__ double sd[256];
    double s = 0.0;
    for (int n = threadIdx.x; n < N_TXT; n += 256) s += (double)g_rowsum[n];
    sd[threadIdx.x] = s;
    __syncthreads();
    #pragma unroll
    for (int o = 128; o > 0; o >>= 1) {
        if (threadIdx.x < o) sd[threadIdx.x] += sd[threadIdx.x + o];
        __syncthreads();
    }
    if (threadIdx.x == 0) out_loss[0] = (float)(sd[0] / (double)N_TXT);
}

// ---------------------------------------------------------------------------
extern "C" void kernel_launch(void* const* d_in, const int* in_sizes, int n_in,
                              void* d_out, int out_size) {
    const float* img   = (const float*)d_in[0];
    const float* txt   = (const float*)d_in[1];
    const int*   key   = (const int*)d_in[2];
    const float* log_t = (const float*)d_in[3];
    const float* bias  = (const float*)d_in[4];
    float* out = (float*)d_out;
    (void)in_sizes; (void)n_in; (void)out_size;

    float* out_sel  = out + OFF_SEL;
    float* out_zimg = out + OFF_ZIMG;
    float* out_ztxt = out + OFF_ZTXT;
    float* out_ap   = out + OFF_AP;
    float* out_fl   = out + OFF_FL;

    static int smem_cfg = 0;
    const int smem_bytes = NSTAGE * STAGE_SB;   // 81920
    if (!smem_cfg) {
        cudaFuncSetAttribute(gemm_hmma_kernel,
                             cudaFuncAttributeMaxDynamicSharedMemorySize, smem_bytes);
        smem_cfg = 1;
    }

    init_kernel<<<(N_TXT + 255) / 256, 256>>>();
    detect_key_kernel<<<(S_IMG / 2 + 255) / 256, 256>>>(key);
    norm_img_kernel<<<S_IMG, 128>>>(img, out_zimg);
    norm_txt_kernel<<<N_TXT, 128>>>(txt, out_ztxt);

    dim3 grid(N_TXT / 128, S_IMG / 128);
    gemm_hmma_kernel<<<grid, 256, smem_bytes>>>(out_ap, log_t, bias);

    tp_kernel<<<(S_IMG * 32 + 255) / 256, 256>>>(key, log_t, bias);
    argmin_kernel<<<(S_IMG + 255) / 256, 256>>>(key);
    sel_kernel<<<(N_TXT + 255) / 256, 256>>>(out_sel);

    final_kernel<<<N_TXT, 256>>>(out_ap, out_fl, bias);
    loss_kernel<<<1, 256>>>(out);
}

// round 12
// speedup vs baseline: 1.5405x; 1.2304x over previous
#include <cuda_runtime.h>
#include <cuda_fp16.h>
#include <math.h>
#include <stdint.h>

#define S_IMG 16384
#define N_TXT 4096
#define DIM   512

// d_out layout (floats): [loss(1) | sel(4096) | zimg | ztxt | all_pairs | final_logits]
static const size_t OFF_SEL  = 1;
static const size_t OFF_ZIMG = 4097;
static const size_t OFF_ZTXT = 8392705;
static const size_t OFF_AP   = 10489857;   // ODD -> d_out+OFF_AP only 4B-aligned!
static const size_t OFF_FL   = 77598721;   // ODD as well

// ---------------- device scratch (aligned for vector/cp.async access) -------
__device__ __align__(256) float   g_zimg[(size_t)S_IMG * DIM];
__device__ __align__(256) float   g_ztxt[(size_t)N_TXT * DIM];
__device__ __align__(256) __half  g_zimg_h[(size_t)S_IMG * DIM];
__device__ __align__(256) __half  g_ztxt_h[(size_t)N_TXT * DIM];
__device__ float          g_pploss[S_IMG];
__device__ unsigned       g_segmin[N_TXT];
__device__ int            g_sel[N_TXT];
__device__ float          g_rowsum[N_TXT];
__device__ int            g_key_is64;

__device__ __forceinline__ float softplus_f(float z) {
    return fmaxf(z, 0.0f) + log1pf(expf(-fabsf(z)));
}
__device__ __forceinline__ int load_key(const int* __restrict__ key, int i) {
    return g_key_is64 ? key[2 * i] : key[i];
}

// ---------------- portable PTX helpers (compute_103-safe) ----------------
__device__ __forceinline__ uint32_t smem_u32(const void* p) {
    uint32_t a;
    asm("{ .reg .u64 t; cvta.to.shared.u64 t, %1; cvt.u32.u64 %0, t; }" : "=r"(a) : "l"(p));
    return a;
}
__device__ __forceinline__ void cp_async16(uint32_t dst, const void* src) {
    asm volatile("cp.async.cg.shared.global [%0], [%1], 16;" :: "r"(dst), "l"(src));
}
#define CP_COMMIT() asm volatile("cp.async.commit_group;" ::: "memory")
#define CP_WAIT0()  asm volatile("cp.async.wait_group 0;" ::: "memory")
#define CP_WAIT1()  asm volatile("cp.async.wait_group 1;" ::: "memory")

__device__ __forceinline__ void ldmat_x4(uint32_t addr, uint32_t* r) {
    asm volatile("ldmatrix.sync.aligned.m8n8.x4.shared.b16 {%0,%1,%2,%3}, [%4];"
                 : "=r"(r[0]), "=r"(r[1]), "=r"(r[2]), "=r"(r[3]) : "r"(addr));
}
__device__ __forceinline__ void mma16816(float* c, const uint32_t* a, const uint32_t* b) {
    asm volatile(
        "mma.sync.aligned.m16n8k16.row.col.f32.f16.f16.f32 "
        "{%0,%1,%2,%3}, {%4,%5,%6,%7}, {%8,%9}, {%0,%1,%2,%3};"
        : "+f"(c[0]), "+f"(c[1]), "+f"(c[2]), "+f"(c[3])
        : "r"(a[0]), "r"(a[1]), "r"(a[2]), "r"(a[3]), "r"(b[0]), "r"(b[1]));
}
__device__ __forceinline__ void sts64(uint32_t addr, float x, float y) {
    asm volatile("st.shared.v2.f32 [%0], {%1, %2};" :: "r"(addr), "f"(x), "f"(y));
}
__device__ __forceinline__ void lds64(uint32_t addr, float& x, float& y) {
    asm volatile("ld.shared.v2.f32 {%0, %1}, [%2];" : "=f"(x), "=f"(y) : "r"(addr));
}

// ---------------------------------------------------------------------------
// K0: init + key dtype probe
// ---------------------------------------------------------------------------
__global__ void init_kernel() {
    int i = blockIdx.x * blockDim.x + threadIdx.x;
    if (i == 0) g_key_is64 = 1;
    if (i < N_TXT) {
        g_segmin[i] = 0x7F800000u;
        g_sel[i]    = S_IMG;
    }
}
__global__ void detect_key_kernel(const int* __restrict__ key32) {
    int i = blockIdx.x * blockDim.x + threadIdx.x;
    if (i < S_IMG / 2 && key32[2 * i + 1] != 0)
        atomicExch(&g_key_is64, 0);
}

// ---------------------------------------------------------------------------
// K1/K2: normalize -> fp32 scratch + fp16 + d_out copy
// ---------------------------------------------------------------------------
__global__ void norm_img_kernel(const float* __restrict__ in, float* __restrict__ out_region) {
    const int row = blockIdx.x, t = threadIdx.x;
    float4 x = ((const float4*)(in + (size_t)row * DIM))[t];
    float ss = x.x * x.x + x.y * x.y + x.z * x.z + x.w * x.w;
    #pragma unroll
    for (int o = 16; o > 0; o >>= 1) ss += __shfl_xor_sync(0xFFFFFFFFu, ss, o);
    __shared__ float w[4];
    if ((t & 31) == 0) w[t >> 5] = ss;
    __syncthreads();
    float sc = 1.0f / (sqrtf(w[0] + w[1] + w[2] + w[3]) + 1e-12f);
    float y[4] = {x.x * sc, x.y * sc, x.z * sc, x.w * sc};
    ((float4*)(g_zimg + (size_t)row * DIM))[t] = make_float4(y[0], y[1], y[2], y[3]);
    size_t base = (size_t)row * DIM + (size_t)t * 4;
    #pragma unroll
    for (int e = 0; e < 4; e++) {
        g_zimg_h[base + e] = __float2half_rn(y[e]);
        out_region[base + e] = y[e];   // scalar: region only 4B-aligned
    }
}
__global__ void norm_txt_kernel(const float* __restrict__ in, float* __restrict__ out_region) {
    const int row = blockIdx.x, t = threadIdx.x;
    float4 x = ((const float4*)(in + (size_t)row * DIM))[t];
    float ss = x.x * x.x + x.y * x.y + x.z * x.z + x.w * x.w;
    #pragma unroll
    for (int o = 16; o > 0; o >>= 1) ss += __shfl_xor_sync(0xFFFFFFFFu, ss, o);
    __shared__ float w[4];
    if ((t & 31) == 0) w[t >> 5] = ss;
    __syncthreads();
    float sc = 1.0f / (sqrtf(w[0] + w[1] + w[2] + w[3]) + 1e-12f);
    float y[4] = {x.x * sc, x.y * sc, x.z * sc, x.w * sc};
    ((float4*)(g_ztxt + (size_t)row * DIM))[t] = make_float4(y[0], y[1], y[2], y[3]);
    size_t base = (size_t)row * DIM + (size_t)t * 4;
    #pragma unroll
    for (int e = 0; e < 4; e++) {
        g_ztxt_h[base + e] = __float2half_rn(y[e]);
        out_region[base + e] = y[e];
    }
}

// ---------------------------------------------------------------------------
// K3: HMMA GEMM  C[m,n] = (ah.bh) * t + bias   (single fp16 pass)
// 128x128 CTA tile, 256 threads (2x4 warps, 64x32 per warp), BK=64, 3 stages
// Row = 128B data + 16B pad = 144B. smem/stage: 2 x 128 x 144 = 36864 B
// Epilogue: stage C tile in (dead) pipeline smem -> coalesced scalar stores.
// ---------------------------------------------------------------------------
#define BK        64
#define ROW_B     144
#define TILE_SB   (128 * ROW_B)   // 18432
#define STAGE_SB  (2 * TILE_SB)   // 36864
#define NSTAGE    3
#define KSTEPS    (DIM / BK)      // 8
#define EP_ROW_B  528             // 128 floats + 16B pad

__device__ __forceinline__ void load_stage(uint32_t smBase, int stage,
                                           const __half* Ah, const __half* Bh,
                                           int k0, int tid) {
    const uint32_t base = smBase + stage * STAGE_SB;
    // 2 tiles x 128 rows x 8 chunks(16B) = 2048 ops; 256 threads x 8
    #pragma unroll
    for (int j = 0; j < 8; j++) {
        int idx = j * 256 + tid;         // 0..2047
        int row = idx >> 3;              // 0..255
        int chunk = idx & 7;             // 0..7 (16B each)
        uint32_t soff = (uint32_t)(row & 127) * ROW_B + chunk * 16;
        if (row < 128)
            cp_async16(base + soff, Ah + (size_t)row * DIM + k0 + chunk * 8);
        else
            cp_async16(base + TILE_SB + soff, Bh + (size_t)(row - 128) * DIM + k0 + chunk * 8);
    }
}

__global__ void __launch_bounds__(256, 2)
gemm_hmma_kernel(float* __restrict__ C,
                 const float* __restrict__ log_t_p,
                 const float* __restrict__ bias_p) {
    extern __shared__ char smem[];
    const uint32_t smBase = smem_u32(smem);
    const int tid  = threadIdx.x;
    const int wid  = tid >> 5;
    const int lane = tid & 31;
    const int warp_m = wid & 1;        // 0..1 -> 64-row slab
    const int warp_n = wid >> 1;       // 0..3 -> 32-col slab
    const int rowBase = blockIdx.y * 128;
    const int colBase = blockIdx.x * 128;

    const __half* Ah = g_zimg_h + (size_t)rowBase * DIM;
    const __half* Bh = g_ztxt_h + (size_t)colBase * DIM;

    float acc[4][4][4];
    #pragma unroll
    for (int i = 0; i < 4; i++)
        #pragma unroll
        for (int j = 0; j < 4; j++)
            #pragma unroll
            for (int f = 0; f < 4; f++) acc[i][j][f] = 0.0f;

    const uint32_t aoff = (uint32_t)((warp_m * 64 + (lane & 15)) * ROW_B + (lane >> 4) * 16);
    const uint32_t boff = (uint32_t)(TILE_SB +
                                     (warp_n * 32 + (lane & 7) + ((lane >> 4) << 3)) * ROW_B +
                                     ((lane >> 3) & 1) * 16);

    load_stage(smBase, 0, Ah, Bh, 0 * BK, tid); CP_COMMIT();
    load_stage(smBase, 1, Ah, Bh, 1 * BK, tid); CP_COMMIT();

    #pragma unroll 1
    for (int ks = 0; ks < KSTEPS; ks++) {
        if (ks == KSTEPS - 1) { CP_WAIT0(); } else { CP_WAIT1(); }
        __syncthreads();
        if (ks + 2 < KSTEPS) {
            load_stage(smBase, (ks + 2) % NSTAGE, Ah, Bh, (ks + 2) * BK, tid);
            CP_COMMIT();
        }

        const uint32_t st = smBase + (ks % NSTAGE) * STAGE_SB;

        #pragma unroll
        for (int kk = 0; kk < 4; kk++) {   // four k16 sub-steps within BK=64
            uint32_t af[4][4], bfr[2][4];
            #pragma unroll
            for (int i = 0; i < 4; i++)
                ldmat_x4(st + aoff + kk * 32 + i * 16 * ROW_B, af[i]);
            #pragma unroll
            for (int j = 0; j < 2; j++)
                ldmat_x4(st + boff + kk * 32 + j * 16 * ROW_B, bfr[j]);
            #pragma unroll
            for (int i = 0; i < 4; i++)
                #pragma unroll
                for (int j = 0; j < 4; j++)
                    mma16816(acc[i][j], af[i], &bfr[j >> 1][(j & 1) * 2]);
        }
    }

    // ---- Epilogue: stage tile in smem (pipeline buffers are dead), then
    //      write coalesced. C base is only 4B-aligned -> scalar STG. ----
    __syncthreads();
    {
        const int mr = warp_m * 64 + (lane >> 2);       // base smem row
        const int nc = warp_n * 32 + 2 * (lane & 3);    // base smem col
        #pragma unroll
        for (int i = 0; i < 4; i++) {
            #pragma unroll
            for (int j = 0; j < 4; j++) {
                uint32_t a0 = smBase + (uint32_t)(mr + i * 16) * EP_ROW_B + (nc + j * 8) * 4;
                uint32_t a1 = a0 + 8u * EP_ROW_B;
                sts64(a0, acc[i][j][0], acc[i][j][1]);
                sts64(a1, acc[i][j][2], acc[i][j][3]);
            }
        }
    }
    __syncthreads();
    {
        const float t = expf(log_t_p[0]);
        const float b = bias_p[0];
        // 8192 float2 slots; 256 threads x 32
        #pragma unroll 4
        for (int ii = 0; ii < 32; ii++) {
            int p = ii * 256 + tid;          // 0..8191
            int row = p >> 6;                // 64 pairs per row
            int pc  = p & 63;
            float x, y;
            lds64(smBase + (uint32_t)row * EP_ROW_B + pc * 8, x, y);
            size_t g = (size_t)(rowBase + row) * N_TXT + colBase + pc * 2;
            C[g]     = x * t + b;
            C[g + 1] = y * t + b;
        }
    }
}

// ---------------------------------------------------------------------------
// K4: exact fp32 true-positive logits (warp per image) + segment min
// ---------------------------------------------------------------------------
__global__ void tp_kernel(const int* __restrict__ key,
                          const float* __restrict__ log_t_p,
                          const float* __restrict__ bias_p) {
    const int gw = (blockIdx.x * blockDim.x + threadIdx.x) >> 5;
    if (gw >= S_IMG) return;
    const int lane = threadIdx.x & 31;
    const int k = load_key(key, gw);
    const float4* a = (const float4*)(g_zimg + (size_t)gw * DIM);
    const float4* v = (const float4*)(g_ztxt + (size_t)k * DIM);
    float s = 0.0f;
    #pragma unroll
    for (int j = 0; j < 4; j++) {
        float4 x = a[lane + 32 * j], y = v[lane + 32 * j];
        s += x.x * y.x + x.y * y.y + x.z * y.z + x.w * y.w;
    }
    #pragma unroll
    for (int o = 16; o > 0; o >>= 1) s += __shfl_xor_sync(0xFFFFFFFFu, s, o);
    if (lane == 0) {
        float lp = s * expf(log_t_p[0]) + bias_p[0];
        float p = softplus_f(-lp);
        g_pploss[gw] = p;
        atomicMin(&g_segmin[k], __float_as_uint(p));
    }
}

// K5: first-index argmin among exact-min matches
__global__ void argmin_kernel(const int* __restrict__ key) {
    int i = blockIdx.x * blockDim.x + threadIdx.x;
    if (i >= S_IMG) return;
    int k = load_key(key, i);
    if (__float_as_uint(g_pploss[i]) == g_segmin[k])
        atomicMin(&g_sel[k], i);
}

// K6: selected indices (as float) to d_out
__global__ void sel_kernel(float* __restrict__ out_sel) {
    int n = blockIdx.x * blockDim.x + threadIdx.x;
    if (n >= N_TXT) return;
    int sv = g_sel[n];
    out_sel[n] = (float)(sv < S_IMG ? sv : -1);
}

// ---------------------------------------------------------------------------
// K7: final_logits = row gather of all_pairs (bias if invalid) + row loss sums
// ---------------------------------------------------------------------------
__global__ void __launch_bounds__(256)
final_kernel(const float* __restrict__ AP, float* __restrict__ FL,
             const float* __restrict__ bias_p) {
    const int n = blockIdx.x;
    const int sv = g_sel[n];
    const bool valid = sv < S_IMG;
    const float b = bias_p[0];
    const float* src = AP + (size_t)(valid ? sv : 0) * N_TXT;

    float sum = 0.0f;
    for (int j = threadIdx.x; j < N_TXT; j += 256) {
        float v = valid ? src[j] : b;
        FL[(size_t)n * N_TXT + j] = v;
        float lbl = (j == n) ? 1.0f : -1.0f;
        sum += softplus_f(-(lbl * v));
    }
    __shared__ float sm[256];
    sm[threadIdx.x] = sum;
    __syncthreads();
    #pragma unroll
    for (int o = 128; o > 0; o >>= 1) {
        if (threadIdx.x < o) sm[threadIdx.x] += sm[threadIdx.x + o];
        __syncthreads();
    }
    if (threadIdx.x == 0) g_rowsum[n] = sm[0];
}

// K8: final loss reduction (double)
__global__ void loss_kernel(float* __restrict__ out_loss) {
    __shared__ double sd[256];
    double s = 0.0;
    for (int n = threadIdx.x; n < N_TXT; n += 256) s += (double)g_rowsum[n];
    sd[threadIdx.x] = s;
    __syncthreads();
    #pragma unroll
    for (int o = 128; o > 0; o >>= 1) {
        if (threadIdx.x < o) sd[threadIdx.x] += sd[threadIdx.x + o];
        __syncthreads();
    }
    if (threadIdx.x == 0) out_loss[0] = (float)(sd[0] / (double)N_TXT);
}

// ---------------------------------------------------------------------------
extern "C" void kernel_launch(void* const* d_in, const int* in_sizes, int n_in,
                              void* d_out, int out_size) {
    const float* img   = (const float*)d_in[0];
    const float* txt   = (const float*)d_in[1];
    const int*   key   = (const int*)d_in[2];
    const float* log_t = (const float*)d_in[3];
    const float* bias  = (const float*)d_in[4];
    float* out = (float*)d_out;
    (void)in_sizes; (void)n_in; (void)out_size;

    float* out_sel  = out + OFF_SEL;
    float* out_zimg = out + OFF_ZIMG;
    float* out_ztxt = out + OFF_ZTXT;
    float* out_ap   = out + OFF_AP;
    float* out_fl   = out + OFF_FL;

    static int smem_cfg = 0;
    const int smem_bytes = NSTAGE * STAGE_SB;   // 110592
    if (!smem_cfg) {
        cudaFuncSetAttribute(gemm_hmma_kernel,
                             cudaFuncAttributeMaxDynamicSharedMemorySize, smem_bytes);
        smem_cfg = 1;
    }

    init_kernel<<<(N_TXT + 255) / 256, 256>>>();
    detect_key_kernel<<<(S_IMG / 2 + 255) / 256, 256>>>(key);
    norm_img_kernel<<<S_IMG, 128>>>(img, out_zimg);
    norm_txt_kernel<<<N_TXT, 128>>>(txt, out_ztxt);

    dim3 grid(N_TXT / 128, S_IMG / 128);
    gemm_hmma_kernel<<<grid, 256, smem_bytes>>>(out_ap, log_t, bias);

    tp_kernel<<<(S_IMG * 32 + 255) / 256, 256>>>(key, log_t, bias);
    argmin_kernel<<<(S_IMG + 255) / 256, 256>>>(key);
    sel_kernel<<<(N_TXT + 255) / 256, 256>>>(out_sel);

    final_kernel<<<N_TXT, 256>>>(out_ap, out_fl, bias);
    loss_kernel<<<1, 256>>>(out);
}

// round 13
// speedup vs baseline: 1.5820x; 1.0270x over previous
#include <cuda_runtime.h>
#include <cuda_fp16.h>
#include <math.h>
#include <stdint.h>

#define S_IMG 16384
#define N_TXT 4096
#define DIM   512

// d_out layout (floats): [loss(1) | sel(4096) | zimg | ztxt | all_pairs | final_logits]
static const size_t OFF_SEL  = 1;
static const size_t OFF_ZIMG = 4097;
static const size_t OFF_ZTXT = 8392705;
static const size_t OFF_AP   = 10489857;   // ODD -> d_out+OFF_AP only 4B-aligned!
static const size_t OFF_FL   = 77598721;   // ODD as well

// ---------------- device scratch (aligned for vector/cp.async access) -------
__device__ __align__(256) float   g_zimg[(size_t)S_IMG * DIM];
__device__ __align__(256) float   g_ztxt[(size_t)N_TXT * DIM];
__device__ __align__(256) __half  g_zimg_h[(size_t)S_IMG * DIM];
__device__ __align__(256) __half  g_ztxt_h[(size_t)N_TXT * DIM];
__device__ float          g_pploss[S_IMG];
__device__ unsigned       g_segmin[N_TXT];
__device__ int            g_sel[N_TXT];
__device__ float          g_rowsum[N_TXT];
__device__ int            g_key_is64;

__device__ __forceinline__ float softplus_f(float z) {
    return fmaxf(z, 0.0f) + log1pf(expf(-fabsf(z)));
}
__device__ __forceinline__ int load_key(const int* __restrict__ key, int i) {
    return g_key_is64 ? key[2 * i] : key[i];
}

// ---------------- portable PTX helpers (compute_103-safe) ----------------
__device__ __forceinline__ uint32_t smem_u32(const void* p) {
    uint32_t a;
    asm("{ .reg .u64 t; cvta.to.shared.u64 t, %1; cvt.u32.u64 %0, t; }" : "=r"(a) : "l"(p));
    return a;
}
__device__ __forceinline__ void cp_async16(uint32_t dst, const void* src) {
    asm volatile("cp.async.cg.shared.global [%0], [%1], 16;" :: "r"(dst), "l"(src));
}
#define CP_COMMIT() asm volatile("cp.async.commit_group;" ::: "memory")
#define CP_WAIT0()  asm volatile("cp.async.wait_group 0;" ::: "memory")
#define CP_WAIT1()  asm volatile("cp.async.wait_group 1;" ::: "memory")

__device__ __forceinline__ void ldmat_x4(uint32_t addr, uint32_t* r) {
    asm volatile("ldmatrix.sync.aligned.m8n8.x4.shared.b16 {%0,%1,%2,%3}, [%4];"
                 : "=r"(r[0]), "=r"(r[1]), "=r"(r[2]), "=r"(r[3]) : "r"(addr));
}
__device__ __forceinline__ void mma16816(float* c, const uint32_t* a, const uint32_t* b) {
    asm volatile(
        "mma.sync.aligned.m16n8k16.row.col.f32.f16.f16.f32 "
        "{%0,%1,%2,%3}, {%4,%5,%6,%7}, {%8,%9}, {%0,%1,%2,%3};"
        : "+f"(c[0]), "+f"(c[1]), "+f"(c[2]), "+f"(c[3])
        : "r"(a[0]), "r"(a[1]), "r"(a[2]), "r"(a[3]), "r"(b[0]), "r"(b[1]));
}
__device__ __forceinline__ void sts64(uint32_t addr, float x, float y) {
    asm volatile("st.shared.v2.f32 [%0], {%1, %2};" :: "r"(addr), "f"(x), "f"(y));
}
__device__ __forceinline__ void lds64(uint32_t addr, float& x, float& y) {
    asm volatile("ld.shared.v2.f32 {%0, %1}, [%2];" : "=f"(x), "=f"(y) : "r"(addr));
}

// ---------------------------------------------------------------------------
// K0: init + key dtype probe
// ---------------------------------------------------------------------------
__global__ void init_kernel() {
    int i = blockIdx.x * blockDim.x + threadIdx.x;
    if (i == 0) g_key_is64 = 1;
    if (i < N_TXT) {
        g_segmin[i] = 0x7F800000u;
        g_sel[i]    = S_IMG;
    }
}
__global__ void detect_key_kernel(const int* __restrict__ key32) {
    int i = blockIdx.x * blockDim.x + threadIdx.x;
    if (i < S_IMG / 2 && key32[2 * i + 1] != 0)
        atomicExch(&g_key_is64, 0);
}

// ---------------------------------------------------------------------------
// K1/K2: normalize -> fp32 scratch + fp16 + d_out copy
// ---------------------------------------------------------------------------
__global__ void norm_img_kernel(const float* __restrict__ in, float* __restrict__ out_region) {
    const int row = blockIdx.x, t = threadIdx.x;
    float4 x = ((const float4*)(in + (size_t)row * DIM))[t];
    float ss = x.x * x.x + x.y * x.y + x.z * x.z + x.w * x.w;
    #pragma unroll
    for (int o = 16; o > 0; o >>= 1) ss += __shfl_xor_sync(0xFFFFFFFFu, ss, o);
    __shared__ float w[4];
    if ((t & 31) == 0) w[t >> 5] = ss;
    __syncthreads();
    float sc = 1.0f / (sqrtf(w[0] + w[1] + w[2] + w[3]) + 1e-12f);
    float y[4] = {x.x * sc, x.y * sc, x.z * sc, x.w * sc};
    ((float4*)(g_zimg + (size_t)row * DIM))[t] = make_float4(y[0], y[1], y[2], y[3]);
    size_t base = (size_t)row * DIM + (size_t)t * 4;
    #pragma unroll
    for (int e = 0; e < 4; e++) {
        g_zimg_h[base + e] = __float2half_rn(y[e]);
        out_region[base + e] = y[e];   // scalar: region only 4B-aligned
    }
}
__global__ void norm_txt_kernel(const float* __restrict__ in, float* __restrict__ out_region) {
    const int row = blockIdx.x, t = threadIdx.x;
    float4 x = ((const float4*)(in + (size_t)row * DIM))[t];
    float ss = x.x * x.x + x.y * x.y + x.z * x.z + x.w * x.w;
    #pragma unroll
    for (int o = 16; o > 0; o >>= 1) ss += __shfl_xor_sync(0xFFFFFFFFu, ss, o);
    __shared__ float w[4];
    if ((t & 31) == 0) w[t >> 5] = ss;
    __syncthreads();
    float sc = 1.0f / (sqrtf(w[0] + w[1] + w[2] + w[3]) + 1e-12f);
    float y[4] = {x.x * sc, x.y * sc, x.z * sc, x.w * sc};
    ((float4*)(g_ztxt + (size_t)row * DIM))[t] = make_float4(y[0], y[1], y[2], y[3]);
    size_t base = (size_t)row * DIM + (size_t)t * 4;
    #pragma unroll
    for (int e = 0; e < 4; e++) {
        g_ztxt_h[base + e] = __float2half_rn(y[e]);
        out_region[base + e] = y[e];
    }
}

// ---------------------------------------------------------------------------
// K3: HMMA GEMM  C[m,n] = (ah.bh) * t + bias   (single fp16 pass)
// 128x128 CTA tile, 256 threads (2x4 warps, 64x32 per warp), BK=64, 3 stages
// Row = 128B data + 16B pad = 144B. smem/stage: 2 x 128 x 144 = 36864 B
// Epilogue: stage C tile in (dead) pipeline smem -> coalesced scalar stores.
// ---------------------------------------------------------------------------
#define BK        64
#define ROW_B     144
#define TILE_SB   (128 * ROW_B)   // 18432
#define STAGE_SB  (2 * TILE_SB)   // 36864
#define NSTAGE    3
#define KSTEPS    (DIM / BK)      // 8
#define EP_ROW_B  528             // 128 floats + 16B pad

__device__ __forceinline__ void load_stage(uint32_t smBase, int stage,
                                           const __half* Ah, const __half* Bh,
                                           int k0, int tid) {
    const uint32_t base = smBase + stage * STAGE_SB;
    #pragma unroll
    for (int j = 0; j < 8; j++) {
        int idx = j * 256 + tid;         // 0..2047
        int row = idx >> 3;              // 0..255
        int chunk = idx & 7;             // 0..7 (16B each)
        uint32_t soff = (uint32_t)(row & 127) * ROW_B + chunk * 16;
        if (row < 128)
            cp_async16(base + soff, Ah + (size_t)row * DIM + k0 + chunk * 8);
        else
            cp_async16(base + TILE_SB + soff, Bh + (size_t)(row - 128) * DIM + k0 + chunk * 8);
    }
}

__global__ void __launch_bounds__(256, 2)
gemm_hmma_kernel(float* __restrict__ C,
                 const float* __restrict__ log_t_p,
                 const float* __restrict__ bias_p) {
    extern __shared__ char smem[];
    const uint32_t smBase = smem_u32(smem);
    const int tid  = threadIdx.x;
    const int wid  = tid >> 5;
    const int lane = tid & 31;
    const int warp_m = wid & 1;
    const int warp_n = wid >> 1;
    const int rowBase = blockIdx.y * 128;
    const int colBase = blockIdx.x * 128;

    const __half* Ah = g_zimg_h + (size_t)rowBase * DIM;
    const __half* Bh = g_ztxt_h + (size_t)colBase * DIM;

    float acc[4][4][4];
    #pragma unroll
    for (int i = 0; i < 4; i++)
        #pragma unroll
        for (int j = 0; j < 4; j++)
            #pragma unroll
            for (int f = 0; f < 4; f++) acc[i][j][f] = 0.0f;

    const uint32_t aoff = (uint32_t)((warp_m * 64 + (lane & 15)) * ROW_B + (lane >> 4) * 16);
    const uint32_t boff = (uint32_t)(TILE_SB +
                                     (warp_n * 32 + (lane & 7) + ((lane >> 4) << 3)) * ROW_B +
                                     ((lane >> 3) & 1) * 16);

    load_stage(smBase, 0, Ah, Bh, 0 * BK, tid); CP_COMMIT();
    load_stage(smBase, 1, Ah, Bh, 1 * BK, tid); CP_COMMIT();

    #pragma unroll 1
    for (int ks = 0; ks < KSTEPS; ks++) {
        if (ks == KSTEPS - 1) { CP_WAIT0(); } else { CP_WAIT1(); }
        __syncthreads();
        if (ks + 2 < KSTEPS) {
            load_stage(smBase, (ks + 2) % NSTAGE, Ah, Bh, (ks + 2) * BK, tid);
            CP_COMMIT();
        }

        const uint32_t st = smBase + (ks % NSTAGE) * STAGE_SB;

        #pragma unroll
        for (int kk = 0; kk < 4; kk++) {
            uint32_t af[4][4], bfr[2][4];
            #pragma unroll
            for (int i = 0; i < 4; i++)
                ldmat_x4(st + aoff + kk * 32 + i * 16 * ROW_B, af[i]);
            #pragma unroll
            for (int j = 0; j < 2; j++)
                ldmat_x4(st + boff + kk * 32 + j * 16 * ROW_B, bfr[j]);
            #pragma unroll
            for (int i = 0; i < 4; i++)
                #pragma unroll
                for (int j = 0; j < 4; j++)
                    mma16816(acc[i][j], af[i], &bfr[j >> 1][(j & 1) * 2]);
        }
    }

    // ---- Epilogue: stage tile in smem, then write coalesced (scalar STG) ----
    __syncthreads();
    {
        const int mr = warp_m * 64 + (lane >> 2);
        const int nc = warp_n * 32 + 2 * (lane & 3);
        #pragma unroll
        for (int i = 0; i < 4; i++) {
            #pragma unroll
            for (int j = 0; j < 4; j++) {
                uint32_t a0 = smBase + (uint32_t)(mr + i * 16) * EP_ROW_B + (nc + j * 8) * 4;
                uint32_t a1 = a0 + 8u * EP_ROW_B;
                sts64(a0, acc[i][j][0], acc[i][j][1]);
                sts64(a1, acc[i][j][2], acc[i][j][3]);
            }
        }
    }
    __syncthreads();
    {
        const float t = expf(log_t_p[0]);
        const float b = bias_p[0];
        #pragma unroll 4
        for (int ii = 0; ii < 32; ii++) {
            int p = ii * 256 + tid;
            int row = p >> 6;
            int pc  = p & 63;
            float x, y;
            lds64(smBase + (uint32_t)row * EP_ROW_B + pc * 8, x, y);
            size_t g = (size_t)(rowBase + row) * N_TXT + colBase + pc * 2;
            C[g]     = x * t + b;
            C[g + 1] = y * t + b;
        }
    }
}

// ---------------------------------------------------------------------------
// K4: exact fp32 true-positive logits (warp per image) + segment min
// ---------------------------------------------------------------------------
__global__ void tp_kernel(const int* __restrict__ key,
                          const float* __restrict__ log_t_p,
                          const float* __restrict__ bias_p) {
    const int gw = (blockIdx.x * blockDim.x + threadIdx.x) >> 5;
    if (gw >= S_IMG) return;
    const int lane = threadIdx.x & 31;
    const int k = load_key(key, gw);
    const float4* a = (const float4*)(g_zimg + (size_t)gw * DIM);
    const float4* v = (const float4*)(g_ztxt + (size_t)k * DIM);
    float s = 0.0f;
    #pragma unroll
    for (int j = 0; j < 4; j++) {
        float4 x = a[lane + 32 * j], y = v[lane + 32 * j];
        s += x.x * y.x + x.y * y.y + x.z * y.z + x.w * y.w;
    }
    #pragma unroll
    for (int o = 16; o > 0; o >>= 1) s += __shfl_xor_sync(0xFFFFFFFFu, s, o);
    if (lane == 0) {
        float lp = s * expf(log_t_p[0]) + bias_p[0];
        float p = softplus_f(-lp);
        g_pploss[gw] = p;
        atomicMin(&g_segmin[k], __float_as_uint(p));
    }
}

// K5: first-index argmin among exact-min matches
__global__ void argmin_kernel(const int* __restrict__ key) {
    int i = blockIdx.x * blockDim.x + threadIdx.x;
    if (i >= S_IMG) return;
    int k = load_key(key, i);
    if (__float_as_uint(g_pploss[i]) == g_segmin[k])
        atomicMin(&g_sel[k], i);
}

// K6: selected indices (as float) to d_out
__global__ void sel_kernel(float* __restrict__ out_sel) {
    int n = blockIdx.x * blockDim.x + threadIdx.x;
    if (n >= N_TXT) return;
    int sv = g_sel[n];
    out_sel[n] = (float)(sv < S_IMG ? sv : -1);
}

// ---------------------------------------------------------------------------
// K7: final_logits = row gather of all_pairs (bias if invalid) + row loss sums
// ---------------------------------------------------------------------------
__global__ void __launch_bounds__(256)
final_kernel(const float* __restrict__ AP, float* __restrict__ FL,
             const float* __restrict__ bias_p) {
    const int n = blockIdx.x;
    const int sv = g_sel[n];
    const bool valid = sv < S_IMG;
    const float b = bias_p[0];
    const float* src = AP + (size_t)(valid ? sv : 0) * N_TXT;

    float sum = 0.0f;
    for (int j = threadIdx.x; j < N_TXT; j += 256) {
        float v = valid ? src[j] : b;
        FL[(size_t)n * N_TXT + j] = v;
        float lbl = (j == n) ? 1.0f : -1.0f;
        sum += softplus_f(-(lbl * v));
    }
    __shared__ float sm[256];
    sm[threadIdx.x] = sum;
    __syncthreads();
    #pragma unroll
    for (int o = 128; o > 0; o >>= 1) {
        if (threadIdx.x < o) sm[threadIdx.x] += sm[threadIdx.x + o];
        __syncthreads();
    }
    if (threadIdx.x == 0) g_rowsum[n] = sm[0];
}

// K8: final loss reduction (double)
__global__ void loss_kernel(float* __restrict__ out_loss) {
    __shared__ double sd[256];
    double s = 0.0;
    for (int n = threadIdx.x; n < N_TXT; n += 256) s += (double)g_rowsum[n];
    sd[threadIdx.x] = s;
    __syncthreads();
    #pragma unroll
    for (int o = 128; o > 0; o >>= 1) {
        if (threadIdx.x < o) sd[threadIdx.x] += sd[threadIdx.x + o];
        __syncthreads();
    }
    if (threadIdx.x == 0) out_loss[0] = (float)(sd[0] / (double)N_TXT);
}

// ---------------------------------------------------------------------------
extern "C" void kernel_launch(void* const* d_in, const int* in_sizes, int n_in,
                              void* d_out, int out_size) {
    const float* img   = (const float*)d_in[0];
    const float* txt   = (const float*)d_in[1];
    const int*   key   = (const int*)d_in[2];
    const float* log_t = (const float*)d_in[3];
    const float* bias  = (const float*)d_in[4];
    float* out = (float*)d_out;
    (void)in_sizes; (void)n_in; (void)out_size;

    float* out_sel  = out + OFF_SEL;
    float* out_zimg = out + OFF_ZIMG;
    float* out_ztxt = out + OFF_ZTXT;
    float* out_ap   = out + OFF_AP;
    float* out_fl   = out + OFF_FL;

    // One-time setup: smem opt-in + side stream + fork/join events
    static int inited = 0;
    static cudaStream_t s2;
    static cudaEvent_t evFork, evTxt, evImg, evSel;
    const int smem_bytes = NSTAGE * STAGE_SB;   // 110592
    if (!inited) {
        cudaFuncSetAttribute(gemm_hmma_kernel,
                             cudaFuncAttributeMaxDynamicSharedMemorySize, smem_bytes);
        cudaStreamCreateWithFlags(&s2, cudaStreamNonBlocking);
        cudaEventCreateWithFlags(&evFork, cudaEventDisableTiming);
        cudaEventCreateWithFlags(&evTxt,  cudaEventDisableTiming);
        cudaEventCreateWithFlags(&evImg,  cudaEventDisableTiming);
        cudaEventCreateWithFlags(&evSel,  cudaEventDisableTiming);
        inited = 1;
    }

    // Fork: side stream s2 joins the (possibly captured) launch stream's DAG.
    cudaEventRecord(evFork, 0);
    cudaStreamWaitEvent(s2, evFork, 0);

    // s2 chain: init + key probe + txt normalize
    init_kernel<<<(N_TXT + 255) / 256, 256, 0, s2>>>();
    detect_key_kernel<<<(S_IMG / 2 + 255) / 256, 256, 0, s2>>>(key);
    norm_txt_kernel<<<N_TXT, 128, 0, s2>>>(txt, out_ztxt);
    cudaEventRecord(evTxt, s2);

    // s0 chain: img normalize (biggest of the pre-GEMM work)
    norm_img_kernel<<<S_IMG, 128>>>(img, out_zimg);
    cudaEventRecord(evImg, 0);

    // s2: selection chain (needs zimg+ztxt+init+detect; NOT AP) — overlaps GEMM
    cudaStreamWaitEvent(s2, evImg, 0);
    tp_kernel<<<(S_IMG * 32 + 255) / 256, 256, 0, s2>>>(key, log_t, bias);
    argmin_kernel<<<(S_IMG + 255) / 256, 256, 0, s2>>>(key);
    sel_kernel<<<(N_TXT + 255) / 256, 256, 0, s2>>>(out_sel);
    cudaEventRecord(evSel, s2);

    // s0: GEMM (needs both normalizes)
    cudaStreamWaitEvent(0, evTxt, 0);
    dim3 grid(N_TXT / 128, S_IMG / 128);
    gemm_hmma_kernel<<<grid, 256, smem_bytes>>>(out_ap, log_t, bias);

    // Join: final needs AP (s0) + sel (s2)
    cudaStreamWaitEvent(0, evSel, 0);
    final_kernel<<<N_TXT, 256>>>(out_ap, out_fl, bias);
    loss_kernel<<<1, 256>>>(out);
}

// round 14
// speedup vs baseline: 1.6325x; 1.0319x over previous
#include <cuda_runtime.h>
#include <cuda_fp16.h>
#include <math.h>
#include <stdint.h>

#define S_IMG 16384
#define N_TXT 4096
#define DIM   512

// d_out layout (floats): [loss(1) | sel(4096) | zimg | ztxt | all_pairs | final_logits]
static const size_t OFF_SEL  = 1;
static const size_t OFF_ZIMG = 4097;
static const size_t OFF_ZTXT = 8392705;
static const size_t OFF_AP   = 10489857;   // ODD -> d_out+OFF_AP only 4B-aligned!
static const size_t OFF_FL   = 77598721;   // ODD as well

// ---------------- device scratch (aligned for vector/cp.async access) -------
__device__ __align__(256) float   g_zimg[(size_t)S_IMG * DIM];
__device__ __align__(256) float   g_ztxt[(size_t)N_TXT * DIM];
__device__ __align__(256) __half  g_zimg_h[(size_t)S_IMG * DIM];
__device__ __align__(256) __half  g_ztxt_h[(size_t)N_TXT * DIM];
__device__ float          g_pploss[S_IMG];
__device__ unsigned       g_segmin[N_TXT];
__device__ int            g_sel[N_TXT];
__device__ float          g_rowsum[N_TXT];
__device__ int            g_key_is64;

__device__ __forceinline__ float softplus_f(float z) {
    return fmaxf(z, 0.0f) + log1pf(expf(-fabsf(z)));
}
__device__ __forceinline__ int load_key(const int* __restrict__ key, int i) {
    return g_key_is64 ? key[2 * i] : key[i];
}

// ---------------- portable PTX helpers (compute_103-safe) ----------------
__device__ __forceinline__ uint32_t smem_u32(const void* p) {
    uint32_t a;
    asm("{ .reg .u64 t; cvta.to.shared.u64 t, %1; cvt.u32.u64 %0, t; }" : "=r"(a) : "l"(p));
    return a;
}
__device__ __forceinline__ void cp_async16(uint32_t dst, const void* src) {
    asm volatile("cp.async.cg.shared.global [%0], [%1], 16;" :: "r"(dst), "l"(src));
}
#define CP_COMMIT() asm volatile("cp.async.commit_group;" ::: "memory")
#define CP_WAIT0()  asm volatile("cp.async.wait_group 0;" ::: "memory")
#define CP_WAIT1()  asm volatile("cp.async.wait_group 1;" ::: "memory")

__device__ __forceinline__ void ldmat_x4(uint32_t addr, uint32_t* r) {
    asm volatile("ldmatrix.sync.aligned.m8n8.x4.shared.b16 {%0,%1,%2,%3}, [%4];"
                 : "=r"(r[0]), "=r"(r[1]), "=r"(r[2]), "=r"(r[3]) : "r"(addr));
}
__device__ __forceinline__ void mma16816(float* c, const uint32_t* a, const uint32_t* b) {
    asm volatile(
        "mma.sync.aligned.m16n8k16.row.col.f32.f16.f16.f32 "
        "{%0,%1,%2,%3}, {%4,%5,%6,%7}, {%8,%9}, {%0,%1,%2,%3};"
        : "+f"(c[0]), "+f"(c[1]), "+f"(c[2]), "+f"(c[3])
        : "r"(a[0]), "r"(a[1]), "r"(a[2]), "r"(a[3]), "r"(b[0]), "r"(b[1]));
}
__device__ __forceinline__ void sts64(uint32_t addr, float x, float y) {
    asm volatile("st.shared.v2.f32 [%0], {%1, %2};" :: "r"(addr), "f"(x), "f"(y));
}
__device__ __forceinline__ void lds64(uint32_t addr, float& x, float& y) {
    asm volatile("ld.shared.v2.f32 {%0, %1}, [%2];" : "=f"(x), "=f"(y) : "r"(addr));
}

// ---------------------------------------------------------------------------
// K0: init + key dtype probe
// ---------------------------------------------------------------------------
__global__ void init_kernel() {
    int i = blockIdx.x * blockDim.x + threadIdx.x;
    if (i == 0) g_key_is64 = 1;
    if (i < N_TXT) {
        g_segmin[i] = 0x7F800000u;
        g_sel[i]    = S_IMG;
    }
}
__global__ void detect_key_kernel(const int* __restrict__ key32) {
    int i = blockIdx.x * blockDim.x + threadIdx.x;
    if (i < S_IMG / 2 && key32[2 * i + 1] != 0)
        atomicExch(&g_key_is64, 0);
}

// ---------------------------------------------------------------------------
// K1/K2: normalize -> fp32 scratch + fp16 + d_out copy
// ---------------------------------------------------------------------------
__global__ void norm_img_kernel(const float* __restrict__ in, float* __restrict__ out_region) {
    const int row = blockIdx.x, t = threadIdx.x;
    float4 x = ((const float4*)(in + (size_t)row * DIM))[t];
    float ss = x.x * x.x + x.y * x.y + x.z * x.z + x.w * x.w;
    #pragma unroll
    for (int o = 16; o > 0; o >>= 1) ss += __shfl_xor_sync(0xFFFFFFFFu, ss, o);
    __shared__ float w[4];
    if ((t & 31) == 0) w[t >> 5] = ss;
    __syncthreads();
    float sc = 1.0f / (sqrtf(w[0] + w[1] + w[2] + w[3]) + 1e-12f);
    float y[4] = {x.x * sc, x.y * sc, x.z * sc, x.w * sc};
    ((float4*)(g_zimg + (size_t)row * DIM))[t] = make_float4(y[0], y[1], y[2], y[3]);
    size_t base = (size_t)row * DIM + (size_t)t * 4;
    #pragma unroll
    for (int e = 0; e < 4; e++) {
        g_zimg_h[base + e] = __float2half_rn(y[e]);
        out_region[base + e] = y[e];   // scalar: region only 4B-aligned
    }
}
__global__ void norm_txt_kernel(const float* __restrict__ in, float* __restrict__ out_region) {
    const int row = blockIdx.x, t = threadIdx.x;
    float4 x = ((const float4*)(in + (size_t)row * DIM))[t];
    float ss = x.x * x.x + x.y * x.y + x.z * x.z + x.w * x.w;
    #pragma unroll
    for (int o = 16; o > 0; o >>= 1) ss += __shfl_xor_sync(0xFFFFFFFFu, ss, o);
    __shared__ float w[4];
    if ((t & 31) == 0) w[t >> 5] = ss;
    __syncthreads();
    float sc = 1.0f / (sqrtf(w[0] + w[1] + w[2] + w[3]) + 1e-12f);
    float y[4] = {x.x * sc, x.y * sc, x.z * sc, x.w * sc};
    ((float4*)(g_ztxt + (size_t)row * DIM))[t] = make_float4(y[0], y[1], y[2], y[3]);
    size_t base = (size_t)row * DIM + (size_t)t * 4;
    #pragma unroll
    for (int e = 0; e < 4; e++) {
        g_ztxt_h[base + e] = __float2half_rn(y[e]);
        out_region[base + e] = y[e];
    }
}

// ---------------------------------------------------------------------------
// K3: HMMA GEMM  C[m,n] = (ah.bh) * t + bias   (single fp16 pass)
// 128x128 CTA tile, 128 threads = 4 warps (2x2), warp tile 64x64, BK=64,
// 3 stages. Row = 128B data + 16B pad = 144B.
// Epilogue: stage C tile in (dead) pipeline smem -> coalesced scalar stores.
// ---------------------------------------------------------------------------
#define BK        64
#define ROW_B     144
#define TILE_SB   (128 * ROW_B)   // 18432
#define STAGE_SB  (2 * TILE_SB)   // 36864
#define NSTAGE    3
#define KSTEPS    (DIM / BK)      // 8
#define EP_ROW_B  528             // 128 floats + 16B pad
#define GTHREADS  128

__device__ __forceinline__ void load_stage(uint32_t smBase, int stage,
                                           const __half* Ah, const __half* Bh,
                                           int k0, int tid) {
    const uint32_t base = smBase + stage * STAGE_SB;
    // 2 tiles x 128 rows x 8 chunks(16B) = 2048 ops; 128 threads x 16
    #pragma unroll
    for (int j = 0; j < 16; j++) {
        int idx = j * GTHREADS + tid;    // 0..2047
        int row = idx >> 3;              // 0..255
        int chunk = idx & 7;             // 0..7 (16B each)
        uint32_t soff = (uint32_t)(row & 127) * ROW_B + chunk * 16;
        if (row < 128)
            cp_async16(base + soff, Ah + (size_t)row * DIM + k0 + chunk * 8);
        else
            cp_async16(base + TILE_SB + soff, Bh + (size_t)(row - 128) * DIM + k0 + chunk * 8);
    }
}

__global__ void __launch_bounds__(GTHREADS, 2)
gemm_hmma_kernel(float* __restrict__ C,
                 const float* __restrict__ log_t_p,
                 const float* __restrict__ bias_p) {
    extern __shared__ char smem[];
    const uint32_t smBase = smem_u32(smem);
    const int tid  = threadIdx.x;
    const int wid  = tid >> 5;
    const int lane = tid & 31;
    const int warp_m = wid & 1;        // 0..1 -> 64-row slab
    const int warp_n = wid >> 1;       // 0..1 -> 64-col slab
    const int rowBase = blockIdx.y * 128;
    const int colBase = blockIdx.x * 128;

    const __half* Ah = g_zimg_h + (size_t)rowBase * DIM;
    const __half* Bh = g_ztxt_h + (size_t)colBase * DIM;

    float acc[4][8][4];   // [m16][n8][frag] -- 64x64 warp tile
    #pragma unroll
    for (int i = 0; i < 4; i++)
        #pragma unroll
        for (int j = 0; j < 8; j++)
            #pragma unroll
            for (int f = 0; f < 4; f++) acc[i][j][f] = 0.0f;

    const uint32_t aoff = (uint32_t)((warp_m * 64 + (lane & 15)) * ROW_B + (lane >> 4) * 16);
    const uint32_t boff = (uint32_t)(TILE_SB +
                                     (warp_n * 64 + (lane & 7) + ((lane >> 4) << 3)) * ROW_B +
                                     ((lane >> 3) & 1) * 16);

    load_stage(smBase, 0, Ah, Bh, 0 * BK, tid); CP_COMMIT();
    load_stage(smBase, 1, Ah, Bh, 1 * BK, tid); CP_COMMIT();

    #pragma unroll 1
    for (int ks = 0; ks < KSTEPS; ks++) {
        if (ks == KSTEPS - 1) { CP_WAIT0(); } else { CP_WAIT1(); }
        __syncthreads();
        if (ks + 2 < KSTEPS) {
            load_stage(smBase, (ks + 2) % NSTAGE, Ah, Bh, (ks + 2) * BK, tid);
            CP_COMMIT();
        }

        const uint32_t st = smBase + (ks % NSTAGE) * STAGE_SB;

        #pragma unroll
        for (int kk = 0; kk < 4; kk++) {   // four k16 sub-steps within BK=64
            uint32_t af[4][4], bfr[4][4];
            #pragma unroll
            for (int i = 0; i < 4; i++)
                ldmat_x4(st + aoff + kk * 32 + i * 16 * ROW_B, af[i]);
            #pragma unroll
            for (int j = 0; j < 4; j++)
                ldmat_x4(st + boff + kk * 32 + j * 16 * ROW_B, bfr[j]);
            #pragma unroll
            for (int i = 0; i < 4; i++)
                #pragma unroll
                for (int j = 0; j < 8; j++)
                    mma16816(acc[i][j], af[i], &bfr[j >> 1][(j & 1) * 2]);
        }
    }

    // ---- Epilogue: stage tile in smem, then write coalesced (scalar STG) ----
    __syncthreads();
    {
        const int mr = warp_m * 64 + (lane >> 2);
        const int nc = warp_n * 64 + 2 * (lane & 3);
        #pragma unroll
        for (int i = 0; i < 4; i++) {
            #pragma unroll
            for (int j = 0; j < 8; j++) {
                uint32_t a0 = smBase + (uint32_t)(mr + i * 16) * EP_ROW_B + (nc + j * 8) * 4;
                uint32_t a1 = a0 + 8u * EP_ROW_B;
                sts64(a0, acc[i][j][0], acc[i][j][1]);
                sts64(a1, acc[i][j][2], acc[i][j][3]);
            }
        }
    }
    __syncthreads();
    {
        const float t = expf(log_t_p[0]);
        const float b = bias_p[0];
        // 8192 float2 slots; 128 threads x 64
        #pragma unroll 4
        for (int ii = 0; ii < 64; ii++) {
            int p = ii * GTHREADS + tid;     // 0..8191
            int row = p >> 6;                // 64 pairs per row
            int pc  = p & 63;
            float x, y;
            lds64(smBase + (uint32_t)row * EP_ROW_B + pc * 8, x, y);
            size_t g = (size_t)(rowBase + row) * N_TXT + colBase + pc * 2;
            C[g]     = x * t + b;
            C[g + 1] = y * t + b;
        }
    }
}

// ---------------------------------------------------------------------------
// K4: exact fp32 true-positive logits (warp per image) + segment min
// ---------------------------------------------------------------------------
__global__ void tp_kernel(const int* __restrict__ key,
                          const float* __restrict__ log_t_p,
                          const float* __restrict__ bias_p) {
    const int gw = (blockIdx.x * blockDim.x + threadIdx.x) >> 5;
    if (gw >= S_IMG) return;
    const int lane = threadIdx.x & 31;
    const int k = load_key(key, gw);
    const float4* a = (const float4*)(g_zimg + (size_t)gw * DIM);
    const float4* v = (const float4*)(g_ztxt + (size_t)k * DIM);
    float s = 0.0f;
    #pragma unroll
    for (int j = 0; j < 4; j++) {
        float4 x = a[lane + 32 * j], y = v[lane + 32 * j];
        s += x.x * y.x + x.y * y.y + x.z * y.z + x.w * y.w;
    }
    #pragma unroll
    for (int o = 16; o > 0; o >>= 1) s += __shfl_xor_sync(0xFFFFFFFFu, s, o);
    if (lane == 0) {
        float lp = s * expf(log_t_p[0]) + bias_p[0];
        float p = softplus_f(-lp);
        g_pploss[gw] = p;
        atomicMin(&g_segmin[k], __float_as_uint(p));
    }
}

// K5: first-index argmin among exact-min matches
__global__ void argmin_kernel(const int* __restrict__ key) {
    int i = blockIdx.x * blockDim.x + threadIdx.x;
    if (i >= S_IMG) return;
    int k = load_key(key, i);
    if (__float_as_uint(g_pploss[i]) == g_segmin[k])
        atomicMin(&g_sel[k], i);
}

// K6: selected indices (as float) to d_out
__global__ void sel_kernel(float* __restrict__ out_sel) {
    int n = blockIdx.x * blockDim.x + threadIdx.x;
    if (n >= N_TXT) return;
    int sv = g_sel[n];
    out_sel[n] = (float)(sv < S_IMG ? sv : -1);
}

// ---------------------------------------------------------------------------
// K7: final_logits = row gather of all_pairs (bias if invalid) + row loss sums
// ---------------------------------------------------------------------------
__global__ void __launch_bounds__(256)
final_kernel(const float* __restrict__ AP, float* __restrict__ FL,
             const float* __restrict__ bias_p) {
    const int n = blockIdx.x;
    const int sv = g_sel[n];
    const bool valid = sv < S_IMG;
    const float b = bias_p[0];
    const float* src = AP + (size_t)(valid ? sv : 0) * N_TXT;

    float sum = 0.0f;
    for (int j = threadIdx.x; j < N_TXT; j += 256) {
        float v = valid ? src[j] : b;
        FL[(size_t)n * N_TXT + j] = v;
        float lbl = (j == n) ? 1.0f : -1.0f;
        sum += softplus_f(-(lbl * v));
    }
    __shared__ float sm[256];
    sm[threadIdx.x] = sum;
    __syncthreads();
    #pragma unroll
    for (int o = 128; o > 0; o >>= 1) {
        if (threadIdx.x < o) sm[threadIdx.x] += sm[threadIdx.x + o];
        __syncthreads();
    }
    if (threadIdx.x == 0) g_rowsum[n] = sm[0];
}

// K8: final loss reduction (double)
__global__ void loss_kernel(float* __restrict__ out_loss) {
    __shared__ double sd[256];
    double s = 0.0;
    for (int n = threadIdx.x; n < N_TXT; n += 256) s += (double)g_rowsum[n];
    sd[threadIdx.x] = s;
    __syncthreads();
    #pragma unroll
    for (int o = 128; o > 0; o >>= 1) {
        if (threadIdx.x < o) sd[threadIdx.x] += sd[threadIdx.x + o];
        __syncthreads();
    }
    if (threadIdx.x == 0) out_loss[0] = (float)(sd[0] / (double)N_TXT);
}

// ---------------------------------------------------------------------------
extern "C" void kernel_launch(void* const* d_in, const int* in_sizes, int n_in,
                              void* d_out, int out_size) {
    const float* img   = (const float*)d_in[0];
    const float* txt   = (const float*)d_in[1];
    const int*   key   = (const int*)d_in[2];
    const float* log_t = (const float*)d_in[3];
    const float* bias  = (const float*)d_in[4];
    float* out = (float*)d_out;
    (void)in_sizes; (void)n_in; (void)out_size;

    float* out_sel  = out + OFF_SEL;
    float* out_zimg = out + OFF_ZIMG;
    float* out_ztxt = out + OFF_ZTXT;
    float* out_ap   = out + OFF_AP;
    float* out_fl   = out + OFF_FL;

    // One-time setup: smem opt-in + side stream + fork/join events
    static int inited = 0;
    static cudaStream_t s2;
    static cudaEvent_t evFork, evTxt, evImg, evSel;
    const int smem_bytes = NSTAGE * STAGE_SB;   // 110592
    if (!inited) {
        cudaFuncSetAttribute(gemm_hmma_kernel,
                             cudaFuncAttributeMaxDynamicSharedMemorySize, smem_bytes);
        cudaStreamCreateWithFlags(&s2, cudaStreamNonBlocking);
        cudaEventCreateWithFlags(&evFork, cudaEventDisableTiming);
        cudaEventCreateWithFlags(&evTxt,  cudaEventDisableTiming);
        cudaEventCreateWithFlags(&evImg,  cudaEventDisableTiming);
        cudaEventCreateWithFlags(&evSel,  cudaEventDisableTiming);
        inited = 1;
    }

    // Fork: side stream s2 joins the (possibly captured) launch stream's DAG.
    cudaEventRecord(evFork, 0);
    cudaStreamWaitEvent(s2, evFork, 0);

    // s2 chain: init + key probe + txt normalize
    init_kernel<<<(N_TXT + 255) / 256, 256, 0, s2>>>();
    detect_key_kernel<<<(S_IMG / 2 + 255) / 256, 256, 0, s2>>>(key);
    norm_txt_kernel<<<N_TXT, 128, 0, s2>>>(txt, out_ztxt);
    cudaEventRecord(evTxt, s2);

    // s0 chain: img normalize (biggest of the pre-GEMM work)
    norm_img_kernel<<<S_IMG, 128>>>(img, out_zimg);
    cudaEventRecord(evImg, 0);

    // s2: selection chain (needs zimg+ztxt+init+detect; NOT AP) — overlaps GEMM
    cudaStreamWaitEvent(s2, evImg, 0);
    tp_kernel<<<(S_IMG * 32 + 255) / 256, 256, 0, s2>>>(key, log_t, bias);
    argmin_kernel<<<(S_IMG + 255) / 256, 256, 0, s2>>>(key);
    sel_kernel<<<(N_TXT + 255) / 256, 256, 0, s2>>>(out_sel);
    cudaEventRecord(evSel, s2);

    // s0: GEMM (needs both normalizes)
    cudaStreamWaitEvent(0, evTxt, 0);
    dim3 grid(N_TXT / 128, S_IMG / 128);
    gemm_hmma_kernel<<<grid, GTHREADS, smem_bytes>>>(out_ap, log_t, bias);

    // Join: final needs AP (s0) + sel (s2)
    cudaStreamWaitEvent(0, evSel, 0);
    final_kernel<<<N_TXT, 256>>>(out_ap, out_fl, bias);
    loss_kernel<<<1, 256>>>(out);
}

// round 15
// speedup vs baseline: 1.6609x; 1.0174x over previous
#include <cuda_runtime.h>
#include <cuda_fp16.h>
#include <math.h>
#include <stdint.h>

#define S_IMG 16384
#define N_TXT 4096
#define DIM   512

// d_out layout (floats): [loss(1) | sel(4096) | zimg | ztxt | all_pairs | final_logits]
static const size_t OFF_SEL  = 1;
static const size_t OFF_ZIMG = 4097;
static const size_t OFF_ZTXT = 8392705;
static const size_t OFF_AP   = 10489857;   // ODD -> d_out+OFF_AP only 4B-aligned!
static const size_t OFF_FL   = 77598721;   // ODD as well

// ---------------- device scratch (aligned for vector/cp.async access) -------
__device__ __align__(256) __half  g_zimg_h[(size_t)S_IMG * DIM];
__device__ __align__(256) __half  g_ztxt_h[(size_t)N_TXT * DIM];
__device__ float          g_pploss[S_IMG];
__device__ unsigned       g_segmin[N_TXT];
__device__ int            g_sel[N_TXT];
__device__ float          g_rowsum[N_TXT];
__device__ int            g_key_is64;

__device__ __forceinline__ float softplus_f(float z) {        // precise (selection)
    return fmaxf(z, 0.0f) + log1pf(expf(-fabsf(z)));
}
__device__ __forceinline__ float softplus_fast(float z) {     // fast (loss sum)
    return fmaxf(z, 0.0f) + __logf(1.0f + __expf(-fabsf(z)));
}
__device__ __forceinline__ int load_key(const int* __restrict__ key, int i) {
    return g_key_is64 ? key[2 * i] : key[i];
}

// ---------------- portable PTX helpers (compute_103-safe) ----------------
__device__ __forceinline__ uint32_t smem_u32(const void* p) {
    uint32_t a;
    asm("{ .reg .u64 t; cvta.to.shared.u64 t, %1; cvt.u32.u64 %0, t; }" : "=r"(a) : "l"(p));
    return a;
}
__device__ __forceinline__ void cp_async16(uint32_t dst, const void* src) {
    asm volatile("cp.async.cg.shared.global [%0], [%1], 16;" :: "r"(dst), "l"(src));
}
#define CP_COMMIT() asm volatile("cp.async.commit_group;" ::: "memory")
#define CP_WAIT0()  asm volatile("cp.async.wait_group 0;" ::: "memory")
#define CP_WAIT1()  asm volatile("cp.async.wait_group 1;" ::: "memory")

__device__ __forceinline__ void ldmat_x4(uint32_t addr, uint32_t* r) {
    asm volatile("ldmatrix.sync.aligned.m8n8.x4.shared.b16 {%0,%1,%2,%3}, [%4];"
                 : "=r"(r[0]), "=r"(r[1]), "=r"(r[2]), "=r"(r[3]) : "r"(addr));
}
__device__ __forceinline__ void mma16816(float* c, const uint32_t* a, const uint32_t* b) {
    asm volatile(
        "mma.sync.aligned.m16n8k16.row.col.f32.f16.f16.f32 "
        "{%0,%1,%2,%3}, {%4,%5,%6,%7}, {%8,%9}, {%0,%1,%2,%3};"
        : "+f"(c[0]), "+f"(c[1]), "+f"(c[2]), "+f"(c[3])
        : "r"(a[0]), "r"(a[1]), "r"(a[2]), "r"(a[3]), "r"(b[0]), "r"(b[1]));
}
__device__ __forceinline__ void sts64(uint32_t addr, float x, float y) {
    asm volatile("st.shared.v2.f32 [%0], {%1, %2};" :: "r"(addr), "f"(x), "f"(y));
}
__device__ __forceinline__ void lds64(uint32_t addr, float& x, float& y) {
    asm volatile("ld.shared.v2.f32 {%0, %1}, [%2];" : "=f"(x), "=f"(y) : "r"(addr));
}

// ---------------------------------------------------------------------------
// K0: init + key dtype probe
// ---------------------------------------------------------------------------
__global__ void init_kernel() {
    int i = blockIdx.x * blockDim.x + threadIdx.x;
    if (i == 0) g_key_is64 = 1;
    if (i < N_TXT) {
        g_segmin[i] = 0x7F800000u;
        g_sel[i]    = S_IMG;
    }
}
__global__ void detect_key_kernel(const int* __restrict__ key32) {
    int i = blockIdx.x * blockDim.x + threadIdx.x;
    if (i < S_IMG / 2 && key32[2 * i + 1] != 0)
        atomicExch(&g_key_is64, 0);
}

// ---------------------------------------------------------------------------
// K1/K2: normalize -> fp16 scratch + d_out fp32 copy (d_out copy IS the fp32
// master now; tp/final read it back with scalar coalesced loads)
// ---------------------------------------------------------------------------
__global__ void norm_img_kernel(const float* __restrict__ in, float* __restrict__ out_region) {
    const int row = blockIdx.x, t = threadIdx.x;
    float4 x = ((const float4*)(in + (size_t)row * DIM))[t];
    float ss = x.x * x.x + x.y * x.y + x.z * x.z + x.w * x.w;
    #pragma unroll
    for (int o = 16; o > 0; o >>= 1) ss += __shfl_xor_sync(0xFFFFFFFFu, ss, o);
    __shared__ float w[4];
    if ((t & 31) == 0) w[t >> 5] = ss;
    __syncthreads();
    float sc = 1.0f / (sqrtf(w[0] + w[1] + w[2] + w[3]) + 1e-12f);
    float y[4] = {x.x * sc, x.y * sc, x.z * sc, x.w * sc};
    size_t base = (size_t)row * DIM + (size_t)t * 4;
    #pragma unroll
    for (int e = 0; e < 4; e++) {
        g_zimg_h[base + e] = __float2half_rn(y[e]);
        out_region[base + e] = y[e];   // scalar: region only 4B-aligned
    }
}
__global__ void norm_txt_kernel(const float* __restrict__ in, float* __restrict__ out_region) {
    const int row = blockIdx.x, t = threadIdx.x;
    float4 x = ((const float4*)(in + (size_t)row * DIM))[t];
    float ss = x.x * x.x + x.y * x.y + x.z * x.z + x.w * x.w;
    #pragma unroll
    for (int o = 16; o > 0; o >>= 1) ss += __shfl_xor_sync(0xFFFFFFFFu, ss, o);
    __shared__ float w[4];
    if ((t & 31) == 0) w[t >> 5] = ss;
    __syncthreads();
    float sc = 1.0f / (sqrtf(w[0] + w[1] + w[2] + w[3]) + 1e-12f);
    float y[4] = {x.x * sc, x.y * sc, x.z * sc, x.w * sc};
    size_t base = (size_t)row * DIM + (size_t)t * 4;
    #pragma unroll
    for (int e = 0; e < 4; e++) {
        g_ztxt_h[base + e] = __float2half_rn(y[e]);
        out_region[base + e] = y[e];
    }
}

// ---------------------------------------------------------------------------
// K3: HMMA GEMM  C[m,n] = (ah.bh) * t + bias   (single fp16 pass)
// 128x128 CTA tile, 128 threads = 4 warps (2x2), warp tile 64x64, BK=64,
// 3 stages. Row = 128B data + 16B pad = 144B.
// Epilogue: stage C tile in (dead) pipeline smem -> coalesced scalar stores.
// ---------------------------------------------------------------------------
#define BK        64
#define ROW_B     144
#define TILE_SB   (128 * ROW_B)   // 18432
#define STAGE_SB  (2 * TILE_SB)   // 36864
#define NSTAGE    3
#define KSTEPS    (DIM / BK)      // 8
#define EP_ROW_B  528             // 128 floats + 16B pad
#define GTHREADS  128

__device__ __forceinline__ void load_stage(uint32_t smBase, int stage,
                                           const __half* Ah, const __half* Bh,
                                           int k0, int tid) {
    const uint32_t base = smBase + stage * STAGE_SB;
    #pragma unroll
    for (int j = 0; j < 16; j++) {
        int idx = j * GTHREADS + tid;    // 0..2047
        int row = idx >> 3;              // 0..255
        int chunk = idx & 7;             // 0..7 (16B each)
        uint32_t soff = (uint32_t)(row & 127) * ROW_B + chunk * 16;
        if (row < 128)
            cp_async16(base + soff, Ah + (size_t)row * DIM + k0 + chunk * 8);
        else
            cp_async16(base + TILE_SB + soff, Bh + (size_t)(row - 128) * DIM + k0 + chunk * 8);
    }
}

__global__ void __launch_bounds__(GTHREADS, 2)
gemm_hmma_kernel(float* __restrict__ C,
                 const float* __restrict__ log_t_p,
                 const float* __restrict__ bias_p) {
    extern __shared__ char smem[];
    const uint32_t smBase = smem_u32(smem);
    const int tid  = threadIdx.x;
    const int wid  = tid >> 5;
    const int lane = tid & 31;
    const int warp_m = wid & 1;
    const int warp_n = wid >> 1;
    const int rowBase = blockIdx.y * 128;
    const int colBase = blockIdx.x * 128;

    const __half* Ah = g_zimg_h + (size_t)rowBase * DIM;
    const __half* Bh = g_ztxt_h + (size_t)colBase * DIM;

    float acc[4][8][4];
    #pragma unroll
    for (int i = 0; i < 4; i++)
        #pragma unroll
        for (int j = 0; j < 8; j++)
            #pragma unroll
            for (int f = 0; f < 4; f++) acc[i][j][f] = 0.0f;

    const uint32_t aoff = (uint32_t)((warp_m * 64 + (lane & 15)) * ROW_B + (lane >> 4) * 16);
    const uint32_t boff = (uint32_t)(TILE_SB +
                                     (warp_n * 64 + (lane & 7) + ((lane >> 4) << 3)) * ROW_B +
                                     ((lane >> 3) & 1) * 16);

    load_stage(smBase, 0, Ah, Bh, 0 * BK, tid); CP_COMMIT();
    load_stage(smBase, 1, Ah, Bh, 1 * BK, tid); CP_COMMIT();

    #pragma unroll 1
    for (int ks = 0; ks < KSTEPS; ks++) {
        if (ks == KSTEPS - 1) { CP_WAIT0(); } else { CP_WAIT1(); }
        __syncthreads();
        if (ks + 2 < KSTEPS) {
            load_stage(smBase, (ks + 2) % NSTAGE, Ah, Bh, (ks + 2) * BK, tid);
            CP_COMMIT();
        }

        const uint32_t st = smBase + (ks % NSTAGE) * STAGE_SB;

        #pragma unroll
        for (int kk = 0; kk < 4; kk++) {
            uint32_t af[4][4], bfr[4][4];
            #pragma unroll
            for (int i = 0; i < 4; i++)
                ldmat_x4(st + aoff + kk * 32 + i * 16 * ROW_B, af[i]);
            #pragma unroll
            for (int j = 0; j < 4; j++)
                ldmat_x4(st + boff + kk * 32 + j * 16 * ROW_B, bfr[j]);
            #pragma unroll
            for (int i = 0; i < 4; i++)
                #pragma unroll
                for (int j = 0; j < 8; j++)
                    mma16816(acc[i][j], af[i], &bfr[j >> 1][(j & 1) * 2]);
        }
    }

    // ---- Epilogue: stage tile in smem, then write coalesced (scalar STG) ----
    __syncthreads();
    {
        const int mr = warp_m * 64 + (lane >> 2);
        const int nc = warp_n * 64 + 2 * (lane & 3);
        #pragma unroll
        for (int i = 0; i < 4; i++) {
            #pragma unroll
            for (int j = 0; j < 8; j++) {
                uint32_t a0 = smBase + (uint32_t)(mr + i * 16) * EP_ROW_B + (nc + j * 8) * 4;
                uint32_t a1 = a0 + 8u * EP_ROW_B;
                sts64(a0, acc[i][j][0], acc[i][j][1]);
                sts64(a1, acc[i][j][2], acc[i][j][3]);
            }
        }
    }
    __syncthreads();
    {
        const float t = expf(log_t_p[0]);
        const float b = bias_p[0];
        #pragma unroll 4
        for (int ii = 0; ii < 64; ii++) {
            int p = ii * GTHREADS + tid;
            int row = p >> 6;
            int pc  = p & 63;
            float x, y;
            lds64(smBase + (uint32_t)row * EP_ROW_B + pc * 8, x, y);
            size_t g = (size_t)(rowBase + row) * N_TXT + colBase + pc * 2;
            C[g]     = x * t + b;
            C[g + 1] = y * t + b;
        }
    }
}

// ---------------------------------------------------------------------------
// K4: exact fp32 true-positive logits (warp per image) + segment min
// Reads zimg/ztxt from the d_out copies (4B-aligned -> scalar coalesced loads)
// ---------------------------------------------------------------------------
__global__ void tp_kernel(const int* __restrict__ key,
                          const float* __restrict__ zimg,
                          const float* __restrict__ ztxt,
                          const float* __restrict__ log_t_p,
                          const float* __restrict__ bias_p) {
    const int gw = (blockIdx.x * blockDim.x + threadIdx.x) >> 5;
    if (gw >= S_IMG) return;
    const int lane = threadIdx.x & 31;
    const int k = load_key(key, gw);
    const float* a = zimg + (size_t)gw * DIM;
    const float* v = ztxt + (size_t)k * DIM;
    float s = 0.0f;
    #pragma unroll
    for (int j = 0; j < 16; j++)
        s = fmaf(a[lane + 32 * j], v[lane + 32 * j], s);
    #pragma unroll
    for (int o = 16; o > 0; o >>= 1) s += __shfl_xor_sync(0xFFFFFFFFu, s, o);
    if (lane == 0) {
        float lp = s * expf(log_t_p[0]) + bias_p[0];
        float p = softplus_f(-lp);
        g_pploss[gw] = p;
        atomicMin(&g_segmin[k], __float_as_uint(p));
    }
}

// K5: first-index argmin among exact-min matches
__global__ void argmin_kernel(const int* __restrict__ key) {
    int i = blockIdx.x * blockDim.x + threadIdx.x;
    if (i >= S_IMG) return;
    int k = load_key(key, i);
    if (__float_as_uint(g_pploss[i]) == g_segmin[k])
        atomicMin(&g_sel[k], i);
}

// K6: selected indices (as float) to d_out
__global__ void sel_kernel(float* __restrict__ out_sel) {
    int n = blockIdx.x * blockDim.x + threadIdx.x;
    if (n >= N_TXT) return;
    int sv = g_sel[n];
    out_sel[n] = (float)(sv < S_IMG ? sv : -1);
}

// ---------------------------------------------------------------------------
// K7: final_logits = row gather of all_pairs (bias if invalid) + row loss sums
// ---------------------------------------------------------------------------
__global__ void __launch_bounds__(256)
final_kernel(const float* __restrict__ AP, float* __restrict__ FL,
             const float* __restrict__ bias_p) {
    const int n = blockIdx.x;
    const int sv = g_sel[n];
    const bool valid = sv < S_IMG;
    const float b = bias_p[0];
    const float* src = AP + (size_t)(valid ? sv : 0) * N_TXT;

    float sum = 0.0f;
    for (int j = threadIdx.x; j < N_TXT; j += 256) {
        float v = valid ? src[j] : b;
        FL[(size_t)n * N_TXT + j] = v;
        float z = (j == n) ? v : -v;       // label * v
        sum += softplus_fast(-z);
    }
    __shared__ float sm[256];
    sm[threadIdx.x] = sum;
    __syncthreads();
    #pragma unroll
    for (int o = 128; o > 0; o >>= 1) {
        if (threadIdx.x < o) sm[threadIdx.x] += sm[threadIdx.x + o];
        __syncthreads();
    }
    if (threadIdx.x == 0) g_rowsum[n] = sm[0];
}

// K8: final loss reduction (double)
__global__ void loss_kernel(float* __restrict__ out_loss) {
    __shared__ double sd[256];
    double s = 0.0;
    for (int n = threadIdx.x; n < N_TXT; n += 256) s += (double)g_rowsum[n];
    sd[threadIdx.x] = s;
    __syncthreads();
    #pragma unroll
    for (int o = 128; o > 0; o >>= 1) {
        if (threadIdx.x < o) sd[threadIdx.x] += sd[threadIdx.x + o];
        __syncthreads();
    }
    if (threadIdx.x == 0) out_loss[0] = (float)(sd[0] / (double)N_TXT);
}

// ---------------------------------------------------------------------------
extern "C" void kernel_launch(void* const* d_in, const int* in_sizes, int n_in,
                              void* d_out, int out_size) {
    const float* img   = (const float*)d_in[0];
    const float* txt   = (const float*)d_in[1];
    const int*   key   = (const int*)d_in[2];
    const float* log_t = (const float*)d_in[3];
    const float* bias  = (const float*)d_in[4];
    float* out = (float*)d_out;
    (void)in_sizes; (void)n_in; (void)out_size;

    float* out_sel  = out + OFF_SEL;
    float* out_zimg = out + OFF_ZIMG;
    float* out_ztxt = out + OFF_ZTXT;
    float* out_ap   = out + OFF_AP;
    float* out_fl   = out + OFF_FL;

    // One-time setup: smem opt-in + side stream + fork/join events
    static int inited = 0;
    static cudaStream_t s2;
    static cudaEvent_t evFork, evTxt, evImg, evSel;
    const int smem_bytes = NSTAGE * STAGE_SB;   // 110592
    if (!inited) {
        cudaFuncSetAttribute(gemm_hmma_kernel,
                             cudaFuncAttributeMaxDynamicSharedMemorySize, smem_bytes);
        cudaStreamCreateWithFlags(&s2, cudaStreamNonBlocking);
        cudaEventCreateWithFlags(&evFork, cudaEventDisableTiming);
        cudaEventCreateWithFlags(&evTxt,  cudaEventDisableTiming);
        cudaEventCreateWithFlags(&evImg,  cudaEventDisableTiming);
        cudaEventCreateWithFlags(&evSel,  cudaEventDisableTiming);
        inited = 1;
    }

    // Fork: side stream s2 joins the (possibly captured) launch stream's DAG.
    cudaEventRecord(evFork, 0);
    cudaStreamWaitEvent(s2, evFork, 0);

    // s2 chain: init + key probe + txt normalize
    init_kernel<<<(N_TXT + 255) / 256, 256, 0, s2>>>();
    detect_key_kernel<<<(S_IMG / 2 + 255) / 256, 256, 0, s2>>>(key);
    norm_txt_kernel<<<N_TXT, 128, 0, s2>>>(txt, out_ztxt);
    cudaEventRecord(evTxt, s2);

    // s0 chain: img normalize (biggest of the pre-GEMM work)
    norm_img_kernel<<<S_IMG, 128>>>(img, out_zimg);
    cudaEventRecord(evImg, 0);

    // s2: selection chain (needs zimg+ztxt+init+detect; NOT AP) — overlaps GEMM
    cudaStreamWaitEvent(s2, evImg, 0);
    tp_kernel<<<(S_IMG * 32 + 255) / 256, 256, 0, s2>>>(key, out_zimg, out_ztxt, log_t, bias);
    argmin_kernel<<<(S_IMG + 255) / 256, 256, 0, s2>>>(key);
    sel_kernel<<<(N_TXT + 255) / 256, 256, 0, s2>>>(out_sel);
    cudaEventRecord(evSel, s2);

    // s0: GEMM (needs both normalizes)
    cudaStreamWaitEvent(0, evTxt, 0);
    dim3 grid(N_TXT / 128, S_IMG / 128);
    gemm_hmma_kernel<<<grid, GTHREADS, smem_bytes>>>(out_ap, log_t, bias);

    // Join: final needs AP (s0) + sel (s2)
    cudaStreamWaitEvent(0, evSel, 0);
    final_kernel<<<N_TXT, 256>>>(out_ap, out_fl, bias);
    loss_kernel<<<1, 256>>>(out);
}

// round 16
// speedup vs baseline: 1.6886x; 1.0167x over previous
#include <cuda_runtime.h>
#include <cuda_fp16.h>
#include <math.h>
#include <stdint.h>

#define S_IMG 16384
#define N_TXT 4096
#define DIM   512

// d_out layout (floats): [loss(1) | sel(4096) | zimg | ztxt | all_pairs | final_logits]
static const size_t OFF_SEL  = 1;
static const size_t OFF_ZIMG = 4097;
static const size_t OFF_ZTXT = 8392705;
static const size_t OFF_AP   = 10489857;   // ODD -> d_out+OFF_AP only 4B-aligned!
static const size_t OFF_FL   = 77598721;   // ODD as well

// ---------------- device scratch (aligned for vector/cp.async access) -------
__device__ __align__(256) __half  g_zimg_h[(size_t)S_IMG * DIM];
__device__ __align__(256) __half  g_ztxt_h[(size_t)N_TXT * DIM];
__device__ float          g_pploss[S_IMG];
__device__ unsigned       g_segmin[N_TXT];
__device__ int            g_sel[N_TXT];
__device__ float          g_rowsum[N_TXT];
__device__ int            g_key_is64;

__device__ __forceinline__ float softplus_f(float z) {        // precise (selection)
    return fmaxf(z, 0.0f) + log1pf(expf(-fabsf(z)));
}
__device__ __forceinline__ float softplus_fast(float z) {     // fast (loss sum)
    return fmaxf(z, 0.0f) + __logf(1.0f + __expf(-fabsf(z)));
}
__device__ __forceinline__ int load_key(const int* __restrict__ key, int i) {
    return g_key_is64 ? key[2 * i] : key[i];
}

// ---------------- portable PTX helpers (compute_103-safe) ----------------
__device__ __forceinline__ uint32_t smem_u32(const void* p) {
    uint32_t a;
    asm("{ .reg .u64 t; cvta.to.shared.u64 t, %1; cvt.u32.u64 %0, t; }" : "=r"(a) : "l"(p));
    return a;
}
__device__ __forceinline__ void cp_async16(uint32_t dst, const void* src) {
    asm volatile("cp.async.cg.shared.global [%0], [%1], 16;" :: "r"(dst), "l"(src));
}
#define CP_COMMIT() asm volatile("cp.async.commit_group;" ::: "memory")
#define CP_WAIT0()  asm volatile("cp.async.wait_group 0;" ::: "memory")
#define CP_WAIT1()  asm volatile("cp.async.wait_group 1;" ::: "memory")

__device__ __forceinline__ void ldmat_x4(uint32_t addr, uint32_t* r) {
    asm volatile("ldmatrix.sync.aligned.m8n8.x4.shared.b16 {%0,%1,%2,%3}, [%4];"
                 : "=r"(r[0]), "=r"(r[1]), "=r"(r[2]), "=r"(r[3]) : "r"(addr));
}
__device__ __forceinline__ void mma16816(float* c, const uint32_t* a, const uint32_t* b) {
    asm volatile(
        "mma.sync.aligned.m16n8k16.row.col.f32.f16.f16.f32 "
        "{%0,%1,%2,%3}, {%4,%5,%6,%7}, {%8,%9}, {%0,%1,%2,%3};"
        : "+f"(c[0]), "+f"(c[1]), "+f"(c[2]), "+f"(c[3])
        : "r"(a[0]), "r"(a[1]), "r"(a[2]), "r"(a[3]), "r"(b[0]), "r"(b[1]));
}
__device__ __forceinline__ void sts64(uint32_t addr, float x, float y) {
    asm volatile("st.shared.v2.f32 [%0], {%1, %2};" :: "r"(addr), "f"(x), "f"(y));
}
__device__ __forceinline__ void lds64(uint32_t addr, float& x, float& y) {
    asm volatile("ld.shared.v2.f32 {%0, %1}, [%2];" : "=f"(x), "=f"(y) : "r"(addr));
}
__device__ __forceinline__ void stg_cs(float* p, float v) {
    asm volatile("st.global.cs.f32 [%0], %1;" :: "l"(p), "f"(v) : "memory");
}

// ---------------------------------------------------------------------------
// K0: init + key dtype probe
// ---------------------------------------------------------------------------
__global__ void init_kernel() {
    int i = blockIdx.x * blockDim.x + threadIdx.x;
    if (i == 0) g_key_is64 = 1;
    if (i < N_TXT) {
        g_segmin[i] = 0x7F800000u;
        g_sel[i]    = S_IMG;
    }
}
__global__ void detect_key_kernel(const int* __restrict__ key32) {
    int i = blockIdx.x * blockDim.x + threadIdx.x;
    if (i < S_IMG / 2 && key32[2 * i + 1] != 0)
        atomicExch(&g_key_is64, 0);
}

// ---------------------------------------------------------------------------
// K1/K2: normalize -> fp16 scratch + d_out fp32 copy
// Strided per-thread elements [t, t+128, t+256, t+384]: every global load and
// store is fully coalesced (the old contiguous-4 pattern was 25% sectors).
// ---------------------------------------------------------------------------
__global__ void norm_img_kernel(const float* __restrict__ in, float* __restrict__ out_region) {
    const int row = blockIdx.x, t = threadIdx.x;
    const float* src = in + (size_t)row * DIM;
    float x[4];
    float ss = 0.0f;
    #pragma unroll
    for (int e = 0; e < 4; e++) { x[e] = src[t + e * 128]; ss = fmaf(x[e], x[e], ss); }
    #pragma unroll
    for (int o = 16; o > 0; o >>= 1) ss += __shfl_xor_sync(0xFFFFFFFFu, ss, o);
    __shared__ float w[4];
    if ((t & 31) == 0) w[t >> 5] = ss;
    __syncthreads();
    float sc = 1.0f / (sqrtf(w[0] + w[1] + w[2] + w[3]) + 1e-12f);
    size_t base = (size_t)row * DIM + t;
    #pragma unroll
    for (int e = 0; e < 4; e++) {
        float y = x[e] * sc;
        g_zimg_h[base + e * 128] = __float2half_rn(y);
        out_region[base + e * 128] = y;
    }
}
__global__ void norm_txt_kernel(const float* __restrict__ in, float* __restrict__ out_region) {
    const int row = blockIdx.x, t = threadIdx.x;
    const float* src = in + (size_t)row * DIM;
    float x[4];
    float ss = 0.0f;
    #pragma unroll
    for (int e = 0; e < 4; e++) { x[e] = src[t + e * 128]; ss = fmaf(x[e], x[e], ss); }
    #pragma unroll
    for (int o = 16; o > 0; o >>= 1) ss += __shfl_xor_sync(0xFFFFFFFFu, ss, o);
    __shared__ float w[4];
    if ((t & 31) == 0) w[t >> 5] = ss;
    __syncthreads();
    float sc = 1.0f / (sqrtf(w[0] + w[1] + w[2] + w[3]) + 1e-12f);
    size_t base = (size_t)row * DIM + t;
    #pragma unroll
    for (int e = 0; e < 4; e++) {
        float y = x[e] * sc;
        g_ztxt_h[base + e * 128] = __float2half_rn(y);
        out_region[base + e * 128] = y;
    }
}

// ---------------------------------------------------------------------------
// K3: HMMA GEMM  C[m,n] = (ah.bh) * t + bias   (single fp16 pass)
// 128x128 CTA tile, 128 threads = 4 warps (2x2), warp tile 64x64, BK=64,
// 3 stages. Row = 128B data + 16B pad = 144B.
// Epilogue: smem-staged coalesced stores with st.global.cs (evict-first;
// protects the hot A/B input set in L2 from the 268MB C stream).
// ---------------------------------------------------------------------------
#define BK        64
#define ROW_B     144
#define TILE_SB   (128 * ROW_B)   // 18432
#define STAGE_SB  (2 * TILE_SB)   // 36864
#define NSTAGE    3
#define KSTEPS    (DIM / BK)      // 8
#define EP_ROW_B  528             // 128 floats + 16B pad
#define GTHREADS  128

__device__ __forceinline__ void load_stage(uint32_t smBase, int stage,
                                           const __half* Ah, const __half* Bh,
                                           int k0, int tid) {
    const uint32_t base = smBase + stage * STAGE_SB;
    #pragma unroll
    for (int j = 0; j < 16; j++) {
        int idx = j * GTHREADS + tid;    // 0..2047
        int row = idx >> 3;              // 0..255
        int chunk = idx & 7;             // 0..7 (16B each)
        uint32_t soff = (uint32_t)(row & 127) * ROW_B + chunk * 16;
        if (row < 128)
            cp_async16(base + soff, Ah + (size_t)row * DIM + k0 + chunk * 8);
        else
            cp_async16(base + TILE_SB + soff, Bh + (size_t)(row - 128) * DIM + k0 + chunk * 8);
    }
}

__global__ void __launch_bounds__(GTHREADS, 2)
gemm_hmma_kernel(float* __restrict__ C,
                 const float* __restrict__ log_t_p,
                 const float* __restrict__ bias_p) {
    extern __shared__ char smem[];
    const uint32_t smBase = smem_u32(smem);
    const int tid  = threadIdx.x;
    const int wid  = tid >> 5;
    const int lane = tid & 31;
    const int warp_m = wid & 1;
    const int warp_n = wid >> 1;
    const int rowBase = blockIdx.y * 128;
    const int colBase = blockIdx.x * 128;

    const __half* Ah = g_zimg_h + (size_t)rowBase * DIM;
    const __half* Bh = g_ztxt_h + (size_t)colBase * DIM;

    float acc[4][8][4];
    #pragma unroll
    for (int i = 0; i < 4; i++)
        #pragma unroll
        for (int j = 0; j < 8; j++)
            #pragma unroll
            for (int f = 0; f < 4; f++) acc[i][j][f] = 0.0f;

    const uint32_t aoff = (uint32_t)((warp_m * 64 + (lane & 15)) * ROW_B + (lane >> 4) * 16);
    const uint32_t boff = (uint32_t)(TILE_SB +
                                     (warp_n * 64 + (lane & 7) + ((lane >> 4) << 3)) * ROW_B +
                                     ((lane >> 3) & 1) * 16);

    load_stage(smBase, 0, Ah, Bh, 0 * BK, tid); CP_COMMIT();
    load_stage(smBase, 1, Ah, Bh, 1 * BK, tid); CP_COMMIT();

    #pragma unroll 1
    for (int ks = 0; ks < KSTEPS; ks++) {
        if (ks == KSTEPS - 1) { CP_WAIT0(); } else { CP_WAIT1(); }
        __syncthreads();
        if (ks + 2 < KSTEPS) {
            load_stage(smBase, (ks + 2) % NSTAGE, Ah, Bh, (ks + 2) * BK, tid);
            CP_COMMIT();
        }

        const uint32_t st = smBase + (ks % NSTAGE) * STAGE_SB;

        #pragma unroll
        for (int kk = 0; kk < 4; kk++) {
            uint32_t af[4][4], bfr[4][4];
            #pragma unroll
            for (int i = 0; i < 4; i++)
                ldmat_x4(st + aoff + kk * 32 + i * 16 * ROW_B, af[i]);
            #pragma unroll
            for (int j = 0; j < 4; j++)
                ldmat_x4(st + boff + kk * 32 + j * 16 * ROW_B, bfr[j]);
            #pragma unroll
            for (int i = 0; i < 4; i++)
                #pragma unroll
                for (int j = 0; j < 8; j++)
                    mma16816(acc[i][j], af[i], &bfr[j >> 1][(j & 1) * 2]);
        }
    }

    // ---- Epilogue: stage tile in smem, then write coalesced (scalar STG.cs) --
    __syncthreads();
    {
        const int mr = warp_m * 64 + (lane >> 2);
        const int nc = warp_n * 64 + 2 * (lane & 3);
        #pragma unroll
        for (int i = 0; i < 4; i++) {
            #pragma unroll
            for (int j = 0; j < 8; j++) {
                uint32_t a0 = smBase + (uint32_t)(mr + i * 16) * EP_ROW_B + (nc + j * 8) * 4;
                uint32_t a1 = a0 + 8u * EP_ROW_B;
                sts64(a0, acc[i][j][0], acc[i][j][1]);
                sts64(a1, acc[i][j][2], acc[i][j][3]);
            }
        }
    }
    __syncthreads();
    {
        const float t = expf(log_t_p[0]);
        const float b = bias_p[0];
        #pragma unroll 4
        for (int ii = 0; ii < 64; ii++) {
            int p = ii * GTHREADS + tid;
            int row = p >> 6;
            int pc  = p & 63;
            float x, y;
            lds64(smBase + (uint32_t)row * EP_ROW_B + pc * 8, x, y);
            size_t g = (size_t)(rowBase + row) * N_TXT + colBase + pc * 2;
            stg_cs(C + g,     x * t + b);
            stg_cs(C + g + 1, y * t + b);
        }
    }
}

// ---------------------------------------------------------------------------
// K4: exact fp32 true-positive logits (warp per image) + segment min
// ---------------------------------------------------------------------------
__global__ void tp_kernel(const int* __restrict__ key,
                          const float* __restrict__ zimg,
                          const float* __restrict__ ztxt,
                          const float* __restrict__ log_t_p,
                          const float* __restrict__ bias_p) {
    const int gw = (blockIdx.x * blockDim.x + threadIdx.x) >> 5;
    if (gw >= S_IMG) return;
    const int lane = threadIdx.x & 31;
    const int k = load_key(key, gw);
    const float* a = zimg + (size_t)gw * DIM;
    const float* v = ztxt + (size_t)k * DIM;
    float s = 0.0f;
    #pragma unroll
    for (int j = 0; j < 16; j++)
        s = fmaf(a[lane + 32 * j], v[lane + 32 * j], s);
    #pragma unroll
    for (int o = 16; o > 0; o >>= 1) s += __shfl_xor_sync(0xFFFFFFFFu, s, o);
    if (lane == 0) {
        float lp = s * expf(log_t_p[0]) + bias_p[0];
        float p = softplus_f(-lp);
        g_pploss[gw] = p;
        atomicMin(&g_segmin[k], __float_as_uint(p));
    }
}

// K5: first-index argmin among exact-min matches
__global__ void argmin_kernel(const int* __restrict__ key) {
    int i = blockIdx.x * blockDim.x + threadIdx.x;
    if (i >= S_IMG) return;
    int k = load_key(key, i);
    if (__float_as_uint(g_pploss[i]) == g_segmin[k])
        atomicMin(&g_sel[k], i);
}

// K6: selected indices (as float) to d_out
__global__ void sel_kernel(float* __restrict__ out_sel) {
    int n = blockIdx.x * blockDim.x + threadIdx.x;
    if (n >= N_TXT) return;
    int sv = g_sel[n];
    out_sel[n] = (float)(sv < S_IMG ? sv : -1);
}

// ---------------------------------------------------------------------------
// K7: final_logits = row gather of all_pairs (bias if invalid) + row loss sums
// ---------------------------------------------------------------------------
__global__ void __launch_bounds__(256)
final_kernel(const float* __restrict__ AP, float* __restrict__ FL,
             const float* __restrict__ bias_p) {
    const int n = blockIdx.x;
    const int sv = g_sel[n];
    const bool valid = sv < S_IMG;
    const float b = bias_p[0];
    const float* src = AP + (size_t)(valid ? sv : 0) * N_TXT;

    float sum = 0.0f;
    for (int j = threadIdx.x; j < N_TXT; j += 256) {
        float v = valid ? src[j] : b;
        FL[(size_t)n * N_TXT + j] = v;
        float z = (j == n) ? v : -v;       // label * v
        sum += softplus_fast(-z);
    }
    __shared__ float sm[256];
    sm[threadIdx.x] = sum;
    __syncthreads();
    #pragma unroll
    for (int o = 128; o > 0; o >>= 1) {
        if (threadIdx.x < o) sm[threadIdx.x] += sm[threadIdx.x + o];
        __syncthreads();
    }
    if (threadIdx.x == 0) g_rowsum[n] = sm[0];
}

// K8: final loss reduction (double)
__global__ void loss_kernel(float* __restrict__ out_loss) {
    __shared__ double sd[256];
    double s = 0.0;
    for (int n = threadIdx.x; n < N_TXT; n += 256) s += (double)g_rowsum[n];
    sd[threadIdx.x] = s;
    __syncthreads();
    #pragma unroll
    for (int o = 128; o > 0; o >>= 1) {
        if (threadIdx.x < o) sd[threadIdx.x] += sd[threadIdx.x + o];
        __syncthreads();
    }
    if (threadIdx.x == 0) out_loss[0] = (float)(sd[0] / (double)N_TXT);
}

// ---------------------------------------------------------------------------
extern "C" void kernel_launch(void* const* d_in, const int* in_sizes, int n_in,
                              void* d_out, int out_size) {
    const float* img   = (const float*)d_in[0];
    const float* txt   = (const float*)d_in[1];
    const int*   key   = (const int*)d_in[2];
    const float* log_t = (const float*)d_in[3];
    const float* bias  = (const float*)d_in[4];
    float* out = (float*)d_out;
    (void)in_sizes; (void)n_in; (void)out_size;

    float* out_sel  = out + OFF_SEL;
    float* out_zimg = out + OFF_ZIMG;
    float* out_ztxt = out + OFF_ZTXT;
    float* out_ap   = out + OFF_AP;
    float* out_fl   = out + OFF_FL;

    // One-time setup: smem opt-in + side stream + fork/join events
    static int inited = 0;
    static cudaStream_t s2;
    static cudaEvent_t evFork, evTxt, evImg, evSel;
    const int smem_bytes = NSTAGE * STAGE_SB;   // 110592
    if (!inited) {
        cudaFuncSetAttribute(gemm_hmma_kernel,
                             cudaFuncAttributeMaxDynamicSharedMemorySize, smem_bytes);
        cudaStreamCreateWithFlags(&s2, cudaStreamNonBlocking);
        cudaEventCreateWithFlags(&evFork, cudaEventDisableTiming);
        cudaEventCreateWithFlags(&evTxt,  cudaEventDisableTiming);
        cudaEventCreateWithFlags(&evImg,  cudaEventDisableTiming);
        cudaEventCreateWithFlags(&evSel,  cudaEventDisableTiming);
        inited = 1;
    }

    // Fork: side stream s2 joins the (possibly captured) launch stream's DAG.
    cudaEventRecord(evFork, 0);
    cudaStreamWaitEvent(s2, evFork, 0);

    // s2 chain: init + key probe + txt normalize
    init_kernel<<<(N_TXT + 255) / 256, 256, 0, s2>>>();
    detect_key_kernel<<<(S_IMG / 2 + 255) / 256, 256, 0, s2>>>(key);
    norm_txt_kernel<<<N_TXT, 128, 0, s2>>>(txt, out_ztxt);
    cudaEventRecord(evTxt, s2);

    // s0 chain: img normalize (biggest of the pre-GEMM work)
    norm_img_kernel<<<S_IMG, 128>>>(img, out_zimg);
    cudaEventRecord(evImg, 0);

    // s2: selection chain (needs zimg+ztxt+init+detect; NOT AP) — overlaps GEMM
    cudaStreamWaitEvent(s2, evImg, 0);
    tp_kernel<<<(S_IMG * 32 + 255) / 256, 256, 0, s2>>>(key, out_zimg, out_ztxt, log_t, bias);
    argmin_kernel<<<(S_IMG + 255) / 256, 256, 0, s2>>>(key);
    sel_kernel<<<(N_TXT + 255) / 256, 256, 0, s2>>>(out_sel);
    cudaEventRecord(evSel, s2);

    // s0: GEMM (needs both normalizes)
    cudaStreamWaitEvent(0, evTxt, 0);
    dim3 grid(N_TXT / 128, S_IMG / 128);
    gemm_hmma_kernel<<<grid, GTHREADS, smem_bytes>>>(out_ap, log_t, bias);

    // Join: final needs AP (s0) + sel (s2)
    cudaStreamWaitEvent(0, evSel, 0);
    final_kernel<<<N_TXT, 256>>>(out_ap, out_fl, bias);
    loss_kernel<<<1, 256>>>(out);
}